// round 5
// baseline (speedup 1.0000x reference)
#include <cuda_runtime.h>
#include <math.h>

#define T_DIM 256
#define B_DIM 128
#define INP_DIM 768
#define HID 512
#define OUT_DIM 768
#define NL 4
#define G4 (4 * HID)            // 2048
#define ROWS (T_DIM * B_DIM)    // 32768
#define STATE (B_DIM * HID)     // 65536

#define NBLK 128                // persistent recurrence grid (must be <= SM count)
#define WS_STRIDE 68            // padded SMEM stride for W slice (words)
#define HS_STRIDE 36            // padded SMEM stride for h staging (words)

// ---------------- scratch (static device globals: no allocation) ----------------
__device__ float g_seqA[ROWS * HID];      // 64 MB  layer io sequence (ping)
__device__ float g_seqB[ROWS * HID];      // 64 MB  layer io sequence (pong)
__device__ float g_gates[ROWS * G4];      // 256 MB precomputed input-gate contributions
__device__ float g_outp[ROWS * OUT_DIM];  // 96 MB  pre-layernorm output

// grid-barrier state (sense-reversal via generation counter)
__device__ unsigned int g_bar_cnt = 0;
__device__ unsigned int g_bar_gen = 0;

// ============================================================================
// Generic tiled GEMM:  C[M,N] = A[M,K] @ W[N,K]^T + bias1 (+ bias2)
// ============================================================================
__global__ __launch_bounds__(256) void gemm_bt(
    const float* __restrict__ A, const float* __restrict__ W,
    const float* __restrict__ bias1, const float* __restrict__ bias2,
    float* __restrict__ C, int K, int N, int xremap)
{
    __shared__ __align__(16) float As[16][64];
    __shared__ __align__(16) float Bs[16][64];

    const int m0 = blockIdx.x * 64;
    const int n0 = blockIdx.y * 64;
    const int tid = threadIdx.x;

    const int lr = tid >> 2;
    const int lc = (tid & 3) << 2;

    const int arow = m0 + lr;
    long aoff;
    if (xremap) {
        const int b = arow & (B_DIM - 1);
        const int t = arow >> 7;
        aoff = (long)(b * T_DIM + t) * K;
    } else {
        aoff = (long)arow * K;
    }
    const long boff = (long)(n0 + lr) * K;

    const int tm = (tid & 15) << 2;
    const int tn = (tid >> 4) << 2;

    float acc[4][4];
#pragma unroll
    for (int i = 0; i < 4; i++)
#pragma unroll
        for (int j = 0; j < 4; j++) acc[i][j] = 0.f;

    float4 pa = *(const float4*)(A + aoff + lc);
    float4 pb = *(const float4*)(W + boff + lc);

    for (int kc = 0; kc < K; kc += 16) {
        __syncthreads();
        As[lc + 0][lr] = pa.x; As[lc + 1][lr] = pa.y;
        As[lc + 2][lr] = pa.z; As[lc + 3][lr] = pa.w;
        Bs[lc + 0][lr] = pb.x; Bs[lc + 1][lr] = pb.y;
        Bs[lc + 2][lr] = pb.z; Bs[lc + 3][lr] = pb.w;
        __syncthreads();
        if (kc + 16 < K) {
            pa = *(const float4*)(A + aoff + kc + 16 + lc);
            pb = *(const float4*)(W + boff + kc + 16 + lc);
        }
#pragma unroll
        for (int kk = 0; kk < 16; kk++) {
            const float4 av = *(const float4*)&As[kk][tm];
            const float4 bv = *(const float4*)&Bs[kk][tn];
            acc[0][0] += av.x * bv.x; acc[0][1] += av.x * bv.y;
            acc[0][2] += av.x * bv.z; acc[0][3] += av.x * bv.w;
            acc[1][0] += av.y * bv.x; acc[1][1] += av.y * bv.y;
            acc[1][2] += av.y * bv.z; acc[1][3] += av.y * bv.w;
            acc[2][0] += av.z * bv.x; acc[2][1] += av.z * bv.y;
            acc[2][2] += av.z * bv.z; acc[2][3] += av.z * bv.w;
            acc[3][0] += av.w * bv.x; acc[3][1] += av.w * bv.y;
            acc[3][2] += av.w * bv.z; acc[3][3] += av.w * bv.w;
        }
    }

    float bz[4];
#pragma unroll
    for (int j = 0; j < 4; j++) {
        const int n = n0 + tn + j;
        float b = bias1[n];
        if (bias2) b += bias2[n];
        bz[j] = b;
    }
#pragma unroll
    for (int i = 0; i < 4; i++) {
        float4 o;
        o.x = acc[i][0] + bz[0];
        o.y = acc[i][1] + bz[1];
        o.z = acc[i][2] + bz[2];
        o.w = acc[i][3] + bz[3];
        *(float4*)(C + (long)(m0 + tm + i) * N + n0 + tn) = o;
    }
}

// ============================================================================
// Grid-wide barrier. Safe: NBLK=128 blocks, 144KB smem -> 1 block/SM, all
// co-resident on 148 SMs. Generation counter is monotone across replays;
// arrival counter resets inside each barrier (state identical at every entry).
// ============================================================================
__device__ __forceinline__ void grid_barrier()
{
    __threadfence();
    __syncthreads();
    if (threadIdx.x == 0) {
        const unsigned g = *(volatile unsigned int*)&g_bar_gen;
        const unsigned a = atomicAdd(&g_bar_cnt, 1u);
        if (a == NBLK - 1) {
            g_bar_cnt = 0;
            __threadfence();
            *(volatile unsigned int*)&g_bar_gen = g + 1u;
        } else {
            while (*(volatile unsigned int*)&g_bar_gen == g) __nanosleep(32);
        }
    }
    __syncthreads();
}

// ============================================================================
// Persistent LSTM layer: ONE launch runs all 256 timesteps.
// Grid 128 blocks x 128 threads. Block (mb,bb) owns 16 h-cols x 32 batches.
// W_hh slice (64 gate-rows x 512) cached in SMEM once. c stays in registers
// for the whole recurrence. Per step: stage h chunk-wise to SMEM, 4x4
// (gate x batch) register tile, activations, write h, grid barrier.
// ============================================================================
__global__ __launch_bounds__(128, 1) void lstm_layer_kernel(
    const float* __restrict__ h0,    // [B][HID]
    const float* __restrict__ c0,    // [B][HID]
    const float* __restrict__ Whh,   // [2048][512]
    const float* __restrict__ gates, // [T][B][2048]
    float* __restrict__ seq,         // [T][B][HID] layer output
    float* __restrict__ hT,          // [B][HID] -> d_out
    float* __restrict__ cT)          // [B][HID] -> d_out
{
    extern __shared__ float smem[];
    float* ws = smem;                         // [512][WS_STRIDE], cols 0..63 used
    float* hs = smem + 512 * WS_STRIDE;       // [32][HS_STRIDE], cols 0..31 used

    const int tid = threadIdx.x;
    const int mb = blockIdx.x & 31;
    const int bb = blockIdx.x >> 5;
    const int m0 = mb * 16;
    const int b0 = bb * 32;

    // ---- load W slice once: ws[k*WS + mli*4 + g] = Whh[g*512 + m0 + mli][k]
    for (int i = tid; i < 64 * 128; i += 128) {
        const int r = i >> 7;            // 0..63 (row = 4*mli+g ordering below)
        const int kq = i & 127;          // float4 index along k
        const int g = r & 3, mli = r >> 2;
        const float4 v = *(const float4*)(Whh + (long)((g << 9) + m0 + mli) * HID + (kq << 2));
        const int col = mli * 4 + g;
        const int k0 = kq << 2;
        ws[(k0 + 0) * WS_STRIDE + col] = v.x;
        ws[(k0 + 1) * WS_STRIDE + col] = v.y;
        ws[(k0 + 2) * WS_STRIDE + col] = v.z;
        ws[(k0 + 3) * WS_STRIDE + col] = v.w;
    }

    // compute roles: thread = (ml 0..15, bq 0..7) -> 4 gates x 4 batches
    const int ml = tid & 15;
    const int bq = tid >> 4;
    const int m = m0 + ml;
    // h staging roles
    const int hb = tid >> 2;             // 0..31
    const int hkb = (tid & 3) << 3;      // 0,8,16,24

    // cell state registers for batches b0+bq*4+j, column m
    float creg[4];
#pragma unroll
    for (int j = 0; j < 4; j++)
        creg[j] = c0[(long)(b0 + bq * 4 + j) * HID + m];

    __syncthreads();   // ws ready

    const float* hsrc = h0;
    for (int t = 0; t < T_DIM; t++) {
        // prefetch precomputed input-gate contributions (DRAM) early
        const float* pre = gates + (long)t * B_DIM * G4;
        float pg[4][4];
#pragma unroll
        for (int g = 0; g < 4; g++)
#pragma unroll
            for (int j = 0; j < 4; j++)
                pg[g][j] = __ldcg(pre + (long)(b0 + bq * 4 + j) * G4 + (g << 9) + m);

        float acc[4][4];
#pragma unroll
        for (int g = 0; g < 4; g++)
#pragma unroll
            for (int j = 0; j < 4; j++) acc[g][j] = 0.f;

        const float* hp = hsrc + (long)(b0 + hb) * HID + hkb;
        float4 ha = __ldcg((const float4*)hp);
        float4 hc = __ldcg((const float4*)(hp + 4));

        for (int kc = 0; kc < HID; kc += 32) {
            __syncthreads();
            hs[(hkb + 0) * HS_STRIDE + hb] = ha.x;
            hs[(hkb + 1) * HS_STRIDE + hb] = ha.y;
            hs[(hkb + 2) * HS_STRIDE + hb] = ha.z;
            hs[(hkb + 3) * HS_STRIDE + hb] = ha.w;
            hs[(hkb + 4) * HS_STRIDE + hb] = hc.x;
            hs[(hkb + 5) * HS_STRIDE + hb] = hc.y;
            hs[(hkb + 6) * HS_STRIDE + hb] = hc.z;
            hs[(hkb + 7) * HS_STRIDE + hb] = hc.w;
            __syncthreads();
            if (kc + 32 < HID) {
                ha = __ldcg((const float4*)(hp + kc + 32));
                hc = __ldcg((const float4*)(hp + kc + 36));
            }
            const float* wrow = ws + (long)kc * WS_STRIDE + ml * 4;
#pragma unroll
            for (int kk = 0; kk < 32; kk++) {
                const float4 wv = *(const float4*)(wrow + kk * WS_STRIDE);
                const float4 hv = *(const float4*)(hs + kk * HS_STRIDE + bq * 4);
                acc[0][0] += wv.x * hv.x; acc[0][1] += wv.x * hv.y;
                acc[0][2] += wv.x * hv.z; acc[0][3] += wv.x * hv.w;
                acc[1][0] += wv.y * hv.x; acc[1][1] += wv.y * hv.y;
                acc[1][2] += wv.y * hv.z; acc[1][3] += wv.y * hv.w;
                acc[2][0] += wv.z * hv.x; acc[2][1] += wv.z * hv.y;
                acc[2][2] += wv.z * hv.z; acc[2][3] += wv.z * hv.w;
                acc[3][0] += wv.w * hv.x; acc[3][1] += wv.w * hv.y;
                acc[3][2] += wv.w * hv.z; acc[3][3] += wv.w * hv.w;
            }
        }

        // activations + state update + h write
        float* hrow = seq + (long)t * STATE;
#pragma unroll
        for (int j = 0; j < 4; j++) {
            const int b = b0 + bq * 4 + j;
            // ws layout interleaves gates: acc[g] with g in {i,f,g,o} order 0..3
            const float gi = acc[0][j] + pg[0][j];
            const float gf = acc[1][j] + pg[1][j];
            const float gg = acc[2][j] + pg[2][j];
            const float go = acc[3][j] + pg[3][j];
            const float i_ = 1.f / (1.f + expf(-gi));
            const float f_ = 1.f / (1.f + expf(-gf));
            const float g_ = tanhf(gg);
            const float o_ = 1.f / (1.f + expf(-go));
            const float c = f_ * creg[j] + i_ * g_;
            creg[j] = c;
            const float h = o_ * tanhf(c);
            hrow[(long)b * HID + m] = h;
            if (t == T_DIM - 1) {
                hT[(long)b * HID + m] = h;
                cT[(long)b * HID + m] = c;
            }
        }

        grid_barrier();          // publish h[t] before anyone reads it at t+1
        hsrc = seq + (long)t * STATE;
    }
}

// ============================================================================
// LayerNorm over last dim (768) + transpose rows (t,b) -> (b,t) into d_out.
// ============================================================================
__global__ __launch_bounds__(256) void ln_out_kernel(
    const float* __restrict__ X, const float* __restrict__ gamma,
    const float* __restrict__ beta, float* __restrict__ out)
{
    const int row = blockIdx.x;                 // t*B + b
    const float* x = X + (long)row * OUT_DIM;
    const int tid = threadIdx.x;

    const float v0 = x[tid];
    const float v1 = x[tid + 256];
    const float v2 = x[tid + 512];

    __shared__ float red[8];
    __shared__ float s_mu, s_rs;

    float s = v0 + v1 + v2;
#pragma unroll
    for (int o = 16; o > 0; o >>= 1) s += __shfl_down_sync(0xffffffffu, s, o);
    if ((tid & 31) == 0) red[tid >> 5] = s;
    __syncthreads();
    if (tid == 0) {
        float tot = 0.f;
#pragma unroll
        for (int i = 0; i < 8; i++) tot += red[i];
        s_mu = tot * (1.f / OUT_DIM);
    }
    __syncthreads();
    const float mu = s_mu;
    const float d0 = v0 - mu, d1 = v1 - mu, d2 = v2 - mu;

    float q = d0 * d0 + d1 * d1 + d2 * d2;
#pragma unroll
    for (int o = 16; o > 0; o >>= 1) q += __shfl_down_sync(0xffffffffu, q, o);
    if ((tid & 31) == 0) red[tid >> 5] = q;
    __syncthreads();
    if (tid == 0) {
        float tot = 0.f;
#pragma unroll
        for (int i = 0; i < 8; i++) tot += red[i];
        s_rs = rsqrtf(tot * (1.f / OUT_DIM) + 1e-5f);
    }
    __syncthreads();
    const float rs = s_rs;

    const int b = row & (B_DIM - 1);
    const int t = row >> 7;
    float* o = out + (long)(b * T_DIM + t) * OUT_DIM;
    o[tid]       = d0 * rs * gamma[tid]       + beta[tid];
    o[tid + 256] = d1 * rs * gamma[tid + 256] + beta[tid + 256];
    o[tid + 512] = d2 * rs * gamma[tid + 512] + beta[tid + 512];
}

// ============================================================================
extern "C" void kernel_launch(void* const* d_in, const int* in_sizes, int n_in,
                              void* d_out, int out_size)
{
    const float* x     = (const float*)d_in[0];
    const float* h0    = (const float*)d_in[1];
    const float* c0    = (const float*)d_in[2];
    const float* W_in  = (const float*)d_in[3];
    const float* b_in  = (const float*)d_in[4];
    const float* W_ih  = (const float*)d_in[5];
    const float* W_hh  = (const float*)d_in[6];
    const float* b_ih  = (const float*)d_in[7];
    const float* b_hh  = (const float*)d_in[8];
    const float* W_out = (const float*)d_in[9];
    const float* b_out = (const float*)d_in[10];
    const float* ln_g  = (const float*)d_in[11];
    const float* ln_b  = (const float*)d_in[12];
    float* out = (float*)d_out;

    float *seqA, *seqB, *gates, *outp;
    cudaGetSymbolAddress((void**)&seqA, g_seqA);
    cudaGetSymbolAddress((void**)&seqB, g_seqB);
    cudaGetSymbolAddress((void**)&gates, g_gates);
    cudaGetSymbolAddress((void**)&outp, g_outp);

    const int lstm_smem = (512 * WS_STRIDE + 32 * HS_STRIDE) * (int)sizeof(float);
    cudaFuncSetAttribute(lstm_layer_kernel,
                         cudaFuncAttributeMaxDynamicSharedMemorySize, lstm_smem);

    const long OUT_ELEMS = (long)B_DIM * T_DIM * OUT_DIM;   // 25,165,824

    // 1) input projection with (b,t)->(t,b) transpose
    gemm_bt<<<dim3(ROWS / 64, HID / 64), 256>>>(x, W_in, b_in, nullptr, seqA,
                                                INP_DIM, HID, 1);

    for (int l = 0; l < NL; l++) {
        const float* in = (l & 1) ? seqB : seqA;
        float* outSeq   = (l & 1) ? seqA : seqB;

        // 2a) parallel: gates = in @ W_ih[l]^T + b_ih[l] + b_hh[l]
        gemm_bt<<<dim3(ROWS / 64, G4 / 64), 256>>>(
            in, W_ih + (long)l * G4 * HID, b_ih + l * G4, b_hh + l * G4,
            gates, HID, G4, 0);

        // 2b) serial recurrence: ONE persistent launch for all 256 timesteps
        lstm_layer_kernel<<<NBLK, 128, lstm_smem>>>(
            h0 + (long)l * STATE, c0 + (long)l * STATE,
            W_hh + (long)l * G4 * HID, gates, outSeq,
            out + OUT_ELEMS + (long)l * STATE,
            out + OUT_ELEMS + (long)NL * STATE + (long)l * STATE);
    }

    // 3) output projection (final sequence lives in seqA after 4 layers)
    gemm_bt<<<dim3(ROWS / 64, OUT_DIM / 64), 256>>>(seqA, W_out, b_out, nullptr,
                                                    outp, HID, OUT_DIM, 0);

    // 4) layernorm + transpose into d_out
    ln_out_kernel<<<ROWS, 256>>>(outp, ln_g, ln_b, out);
}

// round 7
// speedup vs baseline: 1.3928x; 1.3928x over previous
#include <cuda_runtime.h>
#include <math.h>
#include <stdint.h>

#define T_DIM 256
#define B_DIM 128
#define INP_DIM 768
#define HID 512
#define OUT_DIM 768
#define NL 4
#define G4 (4 * HID)            // 2048
#define ROWS (T_DIM * B_DIM)    // 32768
#define STATE (B_DIM * HID)     // 65536

#define NBLK 128                // persistent recurrence grid
#define WS_STRIDE 68
#define HS_STRIDE 36

#define GS 24                   // gemm SMEM row stride (16 k + 8 pad)

// ---------------- scratch (static device globals: no allocation) ----------------
__device__ float g_seqA[ROWS * HID];
__device__ float g_seqB[ROWS * HID];
__device__ float g_gates[ROWS * G4];
__device__ float g_outp[ROWS * OUT_DIM];

__device__ unsigned int g_bar_cnt = 0;
__device__ unsigned int g_bar_gen = 0;

// ---------------- tf32 helpers ----------------
__device__ __forceinline__ uint32_t f2tf(float f) {
    uint32_t u;
    asm("cvt.rna.tf32.f32 %0, %1;" : "=r"(u) : "f"(f));
    return u;
}
// Stage one 8-k group with tf32 rounding AND k-interleave:
// physical positions (0..7) hold logical k (0,4,1,5,2,6,3,7).
// Then a float2 at physical offset 2*tig = logical (k=tig, k=tig+4),
// exactly the PTX m16n8k8.tf32 fragment k-pair.
__device__ __forceinline__ void st8tf_ilv(float* p, float4 v0, float4 v1) {
    float4 t0, t1;
    t0.x = __uint_as_float(f2tf(v0.x));   // k0
    t0.y = __uint_as_float(f2tf(v1.x));   // k4
    t0.z = __uint_as_float(f2tf(v0.y));   // k1
    t0.w = __uint_as_float(f2tf(v1.y));   // k5
    t1.x = __uint_as_float(f2tf(v0.z));   // k2
    t1.y = __uint_as_float(f2tf(v1.z));   // k6
    t1.z = __uint_as_float(f2tf(v0.w));   // k3
    t1.w = __uint_as_float(f2tf(v1.w));   // k7
    *(float4*)p = t0;
    *(float4*)(p + 4) = t1;
}
__device__ __forceinline__ void mma8(float& c0, float& c1, float& c2, float& c3,
                                     uint32_t a0, uint32_t a1, uint32_t a2, uint32_t a3,
                                     uint32_t b0, uint32_t b1) {
    asm volatile("mma.sync.aligned.m16n8k8.row.col.f32.tf32.tf32.f32 "
                 "{%0,%1,%2,%3}, {%4,%5,%6,%7}, {%8,%9}, {%0,%1,%2,%3};"
                 : "+f"(c0), "+f"(c1), "+f"(c2), "+f"(c3)
                 : "r"(a0), "r"(a1), "r"(a2), "r"(a3), "r"(b0), "r"(b1));
}

// ============================================================================
// tf32 tensor-core GEMM:  C[M,N] = A[M,K] @ W[N,K]^T + bias1 (+ bias2)
// Block 128x128, 8 warps (2m x 4n), warp tile 64x32, k-chunk 16 (2 x k8 mma).
// SMEM k-interleaved (see st8tf_ilv). Fragment registers per PTX m16n8k8.tf32:
//   a0=(g,t) a1=(g+8,t) a2=(g,t+4) a3=(g+8,t+4); b0=(n=g,k=t) b1=(n=g,k=t+4);
//   c0=(g,2t) c1=(g,2t+1) c2=(g+8,2t) c3=(g+8,2t+1).
// ============================================================================
__global__ __launch_bounds__(256) void gemm_tf32(
    const float* __restrict__ A, const float* __restrict__ W,
    const float* __restrict__ bias1, const float* __restrict__ bias2,
    float* __restrict__ C, int K, int N, int xremap)
{
    __shared__ __align__(16) float As[128 * GS];   // 12 KB
    __shared__ __align__(16) float Bs[128 * GS];   // 12 KB

    const int m0 = blockIdx.x * 128;
    const int n0 = blockIdx.y * 128;
    const int tid = threadIdx.x;
    const int lane = tid & 31;
    const int warp = tid >> 5;
    const int gid = lane >> 2;
    const int tig = lane & 3;
    const int wm = (warp >> 2) * 64;   // 0 or 64
    const int wn = (warp & 3) * 32;    // 0,32,64,96

    // staging role: thread -> one row, one 8-k group
    const int srow = tid >> 1;
    const int skoff = (tid & 1) * 8;
    int arow = m0 + srow;
    if (xremap) {                       // output row r = t*B+b ; source row b*T+t
        const int b = arow & (B_DIM - 1);
        const int t = arow >> 7;
        arow = b * T_DIM + t;
    }
    const float* ag = A + (long)arow * K + skoff;
    const float* bg = W + (long)(n0 + srow) * K + skoff;
    float* adst = &As[srow * GS + skoff];
    float* bdst = &Bs[srow * GS + skoff];

    float acc[4][4][4];
#pragma unroll
    for (int i = 0; i < 4; i++)
#pragma unroll
        for (int j = 0; j < 4; j++)
#pragma unroll
            for (int v = 0; v < 4; v++) acc[i][j][v] = 0.f;

    float4 pa0 = *(const float4*)(ag);
    float4 pa1 = *(const float4*)(ag + 4);
    float4 pb0 = *(const float4*)(bg);
    float4 pb1 = *(const float4*)(bg + 4);

    for (int kc = 0; kc < K; kc += 16) {
        __syncthreads();
        st8tf_ilv(adst, pa0, pa1);
        st8tf_ilv(bdst, pb0, pb1);
        __syncthreads();
        if (kc + 16 < K) {
            pa0 = *(const float4*)(ag + kc + 16);
            pa1 = *(const float4*)(ag + kc + 20);
            pb0 = *(const float4*)(bg + kc + 16);
            pb1 = *(const float4*)(bg + kc + 20);
        }
#pragma unroll
        for (int ks = 0; ks < 16; ks += 8) {
            const int kb = ks + 2 * tig;    // physical offset -> logical (tig, tig+4)
            float2 alo[4], ahi[4], bf[4];
#pragma unroll
            for (int i = 0; i < 4; i++) {
                const float* ap = &As[(wm + i * 16 + gid) * GS + kb];
                alo[i] = *(const float2*)ap;           // row gid:   (a0, a2)
                ahi[i] = *(const float2*)(ap + 8 * GS); // row gid+8: (a1, a3)
            }
#pragma unroll
            for (int j = 0; j < 4; j++)
                bf[j] = *(const float2*)&Bs[(wn + j * 8 + gid) * GS + kb]; // (b0, b1)
#pragma unroll
            for (int i = 0; i < 4; i++)
#pragma unroll
                for (int j = 0; j < 4; j++)
                    mma8(acc[i][j][0], acc[i][j][1], acc[i][j][2], acc[i][j][3],
                         __float_as_uint(alo[i].x), __float_as_uint(ahi[i].x),
                         __float_as_uint(alo[i].y), __float_as_uint(ahi[i].y),
                         __float_as_uint(bf[j].x), __float_as_uint(bf[j].y));
        }
    }

    // epilogue: bias + float2 stores
#pragma unroll
    for (int j = 0; j < 4; j++) {
        const int n = n0 + wn + j * 8 + 2 * tig;
        float bz0 = bias1[n], bz1 = bias1[n + 1];
        if (bias2) { bz0 += bias2[n]; bz1 += bias2[n + 1]; }
#pragma unroll
        for (int i = 0; i < 4; i++) {
            const int m = m0 + wm + i * 16 + gid;
            float2 o1; o1.x = acc[i][j][0] + bz0; o1.y = acc[i][j][1] + bz1;
            float2 o2; o2.x = acc[i][j][2] + bz0; o2.y = acc[i][j][3] + bz1;
            *(float2*)(C + (long)m * N + n) = o1;
            *(float2*)(C + (long)(m + 8) * N + n) = o2;
        }
    }
}

// ============================================================================
// Grid-wide barrier (128 co-resident blocks).
// ============================================================================
__device__ __forceinline__ void grid_barrier()
{
    __threadfence();
    __syncthreads();
    if (threadIdx.x == 0) {
        const unsigned g = *(volatile unsigned int*)&g_bar_gen;
        const unsigned a = atomicAdd(&g_bar_cnt, 1u);
        if (a == NBLK - 1) {
            g_bar_cnt = 0;
            __threadfence();
            *(volatile unsigned int*)&g_bar_gen = g + 1u;
        } else {
            while (*(volatile unsigned int*)&g_bar_gen == g) __nanosleep(32);
        }
    }
    __syncthreads();
}

// ============================================================================
// Persistent LSTM layer (unchanged, passing).
// ============================================================================
__global__ __launch_bounds__(128, 1) void lstm_layer_kernel(
    const float* __restrict__ h0, const float* __restrict__ c0,
    const float* __restrict__ Whh, const float* __restrict__ gates,
    float* __restrict__ seq, float* __restrict__ hT, float* __restrict__ cT)
{
    extern __shared__ float smem[];
    float* ws = smem;
    float* hs = smem + 512 * WS_STRIDE;

    const int tid = threadIdx.x;
    const int mb = blockIdx.x & 31;
    const int bb = blockIdx.x >> 5;
    const int m0 = mb * 16;
    const int b0 = bb * 32;

    for (int i = tid; i < 64 * 128; i += 128) {
        const int r = i >> 7;
        const int kq = i & 127;
        const int g = r & 3, mli = r >> 2;
        const float4 v = *(const float4*)(Whh + (long)((g << 9) + m0 + mli) * HID + (kq << 2));
        const int col = mli * 4 + g;
        const int k0 = kq << 2;
        ws[(k0 + 0) * WS_STRIDE + col] = v.x;
        ws[(k0 + 1) * WS_STRIDE + col] = v.y;
        ws[(k0 + 2) * WS_STRIDE + col] = v.z;
        ws[(k0 + 3) * WS_STRIDE + col] = v.w;
    }

    const int ml = tid & 15;
    const int bq = tid >> 4;
    const int m = m0 + ml;
    const int hb = tid >> 2;
    const int hkb = (tid & 3) << 3;

    float creg[4];
#pragma unroll
    for (int j = 0; j < 4; j++)
        creg[j] = c0[(long)(b0 + bq * 4 + j) * HID + m];

    __syncthreads();

    const float* hsrc = h0;
    for (int t = 0; t < T_DIM; t++) {
        const float* pre = gates + (long)t * B_DIM * G4;
        float pg[4][4];
#pragma unroll
        for (int g = 0; g < 4; g++)
#pragma unroll
            for (int j = 0; j < 4; j++)
                pg[g][j] = __ldcg(pre + (long)(b0 + bq * 4 + j) * G4 + (g << 9) + m);

        float acc[4][4];
#pragma unroll
        for (int g = 0; g < 4; g++)
#pragma unroll
            for (int j = 0; j < 4; j++) acc[g][j] = 0.f;

        const float* hp = hsrc + (long)(b0 + hb) * HID + hkb;
        float4 ha = __ldcg((const float4*)hp);
        float4 hc = __ldcg((const float4*)(hp + 4));

        for (int kc = 0; kc < HID; kc += 32) {
            __syncthreads();
            hs[(hkb + 0) * HS_STRIDE + hb] = ha.x;
            hs[(hkb + 1) * HS_STRIDE + hb] = ha.y;
            hs[(hkb + 2) * HS_STRIDE + hb] = ha.z;
            hs[(hkb + 3) * HS_STRIDE + hb] = ha.w;
            hs[(hkb + 4) * HS_STRIDE + hb] = hc.x;
            hs[(hkb + 5) * HS_STRIDE + hb] = hc.y;
            hs[(hkb + 6) * HS_STRIDE + hb] = hc.z;
            hs[(hkb + 7) * HS_STRIDE + hb] = hc.w;
            __syncthreads();
            if (kc + 32 < HID) {
                ha = __ldcg((const float4*)(hp + kc + 32));
                hc = __ldcg((const float4*)(hp + kc + 36));
            }
            const float* wrow = ws + (long)kc * WS_STRIDE + ml * 4;
#pragma unroll
            for (int kk = 0; kk < 32; kk++) {
                const float4 wv = *(const float4*)(wrow + kk * WS_STRIDE);
                const float4 hv = *(const float4*)(hs + kk * HS_STRIDE + bq * 4);
                acc[0][0] += wv.x * hv.x; acc[0][1] += wv.x * hv.y;
                acc[0][2] += wv.x * hv.z; acc[0][3] += wv.x * hv.w;
                acc[1][0] += wv.y * hv.x; acc[1][1] += wv.y * hv.y;
                acc[1][2] += wv.y * hv.z; acc[1][3] += wv.y * hv.w;
                acc[2][0] += wv.z * hv.x; acc[2][1] += wv.z * hv.y;
                acc[2][2] += wv.z * hv.z; acc[2][3] += wv.z * hv.w;
                acc[3][0] += wv.w * hv.x; acc[3][1] += wv.w * hv.y;
                acc[3][2] += wv.w * hv.z; acc[3][3] += wv.w * hv.w;
            }
        }

        float* hrow = seq + (long)t * STATE;
#pragma unroll
        for (int j = 0; j < 4; j++) {
            const int b = b0 + bq * 4 + j;
            const float gi = acc[0][j] + pg[0][j];
            const float gf = acc[1][j] + pg[1][j];
            const float gg = acc[2][j] + pg[2][j];
            const float go = acc[3][j] + pg[3][j];
            const float i_ = 1.f / (1.f + expf(-gi));
            const float f_ = 1.f / (1.f + expf(-gf));
            const float g_ = tanhf(gg);
            const float o_ = 1.f / (1.f + expf(-go));
            const float c = f_ * creg[j] + i_ * g_;
            creg[j] = c;
            const float h = o_ * tanhf(c);
            hrow[(long)b * HID + m] = h;
            if (t == T_DIM - 1) {
                hT[(long)b * HID + m] = h;
                cT[(long)b * HID + m] = c;
            }
        }

        grid_barrier();
        hsrc = seq + (long)t * STATE;
    }
}

// ============================================================================
// LayerNorm + (t,b)->(b,t) transpose (unchanged).
// ============================================================================
__global__ __launch_bounds__(256) void ln_out_kernel(
    const float* __restrict__ X, const float* __restrict__ gamma,
    const float* __restrict__ beta, float* __restrict__ out)
{
    const int row = blockIdx.x;
    const float* x = X + (long)row * OUT_DIM;
    const int tid = threadIdx.x;

    const float v0 = x[tid];
    const float v1 = x[tid + 256];
    const float v2 = x[tid + 512];

    __shared__ float red[8];
    __shared__ float s_mu, s_rs;

    float s = v0 + v1 + v2;
#pragma unroll
    for (int o = 16; o > 0; o >>= 1) s += __shfl_down_sync(0xffffffffu, s, o);
    if ((tid & 31) == 0) red[tid >> 5] = s;
    __syncthreads();
    if (tid == 0) {
        float tot = 0.f;
#pragma unroll
        for (int i = 0; i < 8; i++) tot += red[i];
        s_mu = tot * (1.f / OUT_DIM);
    }
    __syncthreads();
    const float mu = s_mu;
    const float d0 = v0 - mu, d1 = v1 - mu, d2 = v2 - mu;

    float q = d0 * d0 + d1 * d1 + d2 * d2;
#pragma unroll
    for (int o = 16; o > 0; o >>= 1) q += __shfl_down_sync(0xffffffffu, q, o);
    if ((tid & 31) == 0) red[tid >> 5] = q;
    __syncthreads();
    if (tid == 0) {
        float tot = 0.f;
#pragma unroll
        for (int i = 0; i < 8; i++) tot += red[i];
        s_rs = rsqrtf(tot * (1.f / OUT_DIM) + 1e-5f);
    }
    __syncthreads();
    const float rs = s_rs;

    const int b = row & (B_DIM - 1);
    const int t = row >> 7;
    float* o = out + (long)(b * T_DIM + t) * OUT_DIM;
    o[tid]       = d0 * rs * gamma[tid]       + beta[tid];
    o[tid + 256] = d1 * rs * gamma[tid + 256] + beta[tid + 256];
    o[tid + 512] = d2 * rs * gamma[tid + 512] + beta[tid + 512];
}

// ============================================================================
extern "C" void kernel_launch(void* const* d_in, const int* in_sizes, int n_in,
                              void* d_out, int out_size)
{
    const float* x     = (const float*)d_in[0];
    const float* h0    = (const float*)d_in[1];
    const float* c0    = (const float*)d_in[2];
    const float* W_in  = (const float*)d_in[3];
    const float* b_in  = (const float*)d_in[4];
    const float* W_ih  = (const float*)d_in[5];
    const float* W_hh  = (const float*)d_in[6];
    const float* b_ih  = (const float*)d_in[7];
    const float* b_hh  = (const float*)d_in[8];
    const float* W_out = (const float*)d_in[9];
    const float* b_out = (const float*)d_in[10];
    const float* ln_g  = (const float*)d_in[11];
    const float* ln_b  = (const float*)d_in[12];
    float* out = (float*)d_out;

    float *seqA, *seqB, *gates, *outp;
    cudaGetSymbolAddress((void**)&seqA, g_seqA);
    cudaGetSymbolAddress((void**)&seqB, g_seqB);
    cudaGetSymbolAddress((void**)&gates, g_gates);
    cudaGetSymbolAddress((void**)&outp, g_outp);

    const int lstm_smem = (512 * WS_STRIDE + 32 * HS_STRIDE) * (int)sizeof(float);
    cudaFuncSetAttribute(lstm_layer_kernel,
                         cudaFuncAttributeMaxDynamicSharedMemorySize, lstm_smem);

    const long OUT_ELEMS = (long)B_DIM * T_DIM * OUT_DIM;

    // 1) input projection with (b,t)->(t,b) transpose (tf32 TC)
    gemm_tf32<<<dim3(ROWS / 128, HID / 128), 256>>>(x, W_in, b_in, nullptr, seqA,
                                                    INP_DIM, HID, 1);

    for (int l = 0; l < NL; l++) {
        const float* in = (l & 1) ? seqB : seqA;
        float* outSeq   = (l & 1) ? seqA : seqB;

        // 2a) parallel: gates = in @ W_ih[l]^T + b_ih[l] + b_hh[l] (tf32 TC)
        gemm_tf32<<<dim3(ROWS / 128, G4 / 128), 256>>>(
            in, W_ih + (long)l * G4 * HID, b_ih + l * G4, b_hh + l * G4,
            gates, HID, G4, 0);

        // 2b) serial recurrence: one persistent launch for all 256 timesteps
        lstm_layer_kernel<<<NBLK, 128, lstm_smem>>>(
            h0 + (long)l * STATE, c0 + (long)l * STATE,
            W_hh + (long)l * G4 * HID, gates, outSeq,
            out + OUT_ELEMS + (long)l * STATE,
            out + OUT_ELEMS + (long)NL * STATE + (long)l * STATE);
    }

    // 3) output projection (tf32 TC)
    gemm_tf32<<<dim3(ROWS / 128, OUT_DIM / 128), 256>>>(seqA, W_out, b_out, nullptr,
                                                        outp, HID, OUT_DIM, 0);

    // 4) layernorm + transpose into d_out
    ln_out_kernel<<<ROWS, 256>>>(outp, ln_g, ln_b, out);
}

// round 8
// speedup vs baseline: 1.7959x; 1.2894x over previous
#include <cuda_runtime.h>
#include <cuda_bf16.h>
#include <math.h>
#include <stdint.h>

#define T_DIM 256
#define B_DIM 128
#define INP_DIM 768
#define HID 512
#define OUT_DIM 768
#define NL 4
#define G4 (4 * HID)            // 2048
#define ROWS (T_DIM * B_DIM)    // 32768
#define STATE (B_DIM * HID)     // 65536

#define NBLK 128                // persistent recurrence grid (1 block/SM)
#define GS 24                   // ff-gemm SMEM row stride

// recurrence SMEM plane strides (u32 words). 260 mod 32 == 4 -> fragment LDS
// across a warp (addr = row*260 + t) hits 32 distinct banks.
#define WP 260
#define GXS 36                  // gate-exchange stride (floats), mod 32 == 4

// ---------------- scratch (static device globals: no allocation) ----------------
__device__ float g_seqA[ROWS * HID];
__device__ float g_seqB[ROWS * HID];
__device__ float g_gates[ROWS * G4];
__device__ float g_outp[ROWS * OUT_DIM];
__device__ uint32_t g_hpack[STATE];      // h as packed (bf16 hi | bf16 lo << 16)

__device__ unsigned int g_bar_cnt = 0;
__device__ unsigned int g_bar_gen = 0;

// ---------------- tf32 helpers (FF GEMM, unchanged from passing R7) ----------------
__device__ __forceinline__ uint32_t f2tf(float f) {
    uint32_t u;
    asm("cvt.rna.tf32.f32 %0, %1;" : "=r"(u) : "f"(f));
    return u;
}
__device__ __forceinline__ void st8tf_ilv(float* p, float4 v0, float4 v1) {
    float4 t0, t1;
    t0.x = __uint_as_float(f2tf(v0.x));
    t0.y = __uint_as_float(f2tf(v1.x));
    t0.z = __uint_as_float(f2tf(v0.y));
    t0.w = __uint_as_float(f2tf(v1.y));
    t1.x = __uint_as_float(f2tf(v0.z));
    t1.y = __uint_as_float(f2tf(v1.z));
    t1.z = __uint_as_float(f2tf(v0.w));
    t1.w = __uint_as_float(f2tf(v1.w));
    *(float4*)p = t0;
    *(float4*)(p + 4) = t1;
}
__device__ __forceinline__ void mma8(float& c0, float& c1, float& c2, float& c3,
                                     uint32_t a0, uint32_t a1, uint32_t a2, uint32_t a3,
                                     uint32_t b0, uint32_t b1) {
    asm volatile("mma.sync.aligned.m16n8k8.row.col.f32.tf32.tf32.f32 "
                 "{%0,%1,%2,%3}, {%4,%5,%6,%7}, {%8,%9}, {%0,%1,%2,%3};"
                 : "+f"(c0), "+f"(c1), "+f"(c2), "+f"(c3)
                 : "r"(a0), "r"(a1), "r"(a2), "r"(a3), "r"(b0), "r"(b1));
}

// ---------------- bf16 helpers (recurrence) ----------------
__device__ __forceinline__ void mma16bf(float& c0, float& c1, float& c2, float& c3,
                                        uint32_t a0, uint32_t a1, uint32_t a2, uint32_t a3,
                                        uint32_t b0, uint32_t b1) {
    asm volatile("mma.sync.aligned.m16n8k16.row.col.f32.bf16.bf16.f32 "
                 "{%0,%1,%2,%3}, {%4,%5,%6,%7}, {%8,%9}, {%0,%1,%2,%3};"
                 : "+f"(c0), "+f"(c1), "+f"(c2), "+f"(c3)
                 : "r"(a0), "r"(a1), "r"(a2), "r"(a3), "r"(b0), "r"(b1));
}
// split pair (a,b) into bf16 hi/lo packed pairs (even value in low 16 bits)
__device__ __forceinline__ uint32_t split_pair(float a, float b, uint32_t& lo) {
    __nv_bfloat16 ah = __float2bfloat16_rn(a);
    __nv_bfloat16 bh = __float2bfloat16_rn(b);
    __nv_bfloat16 al = __float2bfloat16_rn(a - __bfloat162float(ah));
    __nv_bfloat16 bl = __float2bfloat16_rn(b - __bfloat162float(bh));
    lo = (uint32_t)__bfloat16_as_ushort(al) | ((uint32_t)__bfloat16_as_ushort(bl) << 16);
    return (uint32_t)__bfloat16_as_ushort(ah) | ((uint32_t)__bfloat16_as_ushort(bh) << 16);
}
// pack one h value as (hi | lo<<16)
__device__ __forceinline__ uint32_t hpk(float h) {
    __nv_bfloat16 hi = __float2bfloat16_rn(h);
    __nv_bfloat16 lo = __float2bfloat16_rn(h - __bfloat162float(hi));
    return (uint32_t)__bfloat16_as_ushort(hi) | ((uint32_t)__bfloat16_as_ushort(lo) << 16);
}

// ============================================================================
// tf32 tensor-core GEMM (unchanged from R7, passing)
// ============================================================================
__global__ __launch_bounds__(256) void gemm_tf32(
    const float* __restrict__ A, const float* __restrict__ W,
    const float* __restrict__ bias1, const float* __restrict__ bias2,
    float* __restrict__ C, int K, int N, int xremap)
{
    __shared__ __align__(16) float As[128 * GS];
    __shared__ __align__(16) float Bs[128 * GS];

    const int m0 = blockIdx.x * 128;
    const int n0 = blockIdx.y * 128;
    const int tid = threadIdx.x;
    const int lane = tid & 31;
    const int warp = tid >> 5;
    const int gid = lane >> 2;
    const int tig = lane & 3;
    const int wm = (warp >> 2) * 64;
    const int wn = (warp & 3) * 32;

    const int srow = tid >> 1;
    const int skoff = (tid & 1) * 8;
    int arow = m0 + srow;
    if (xremap) {
        const int b = arow & (B_DIM - 1);
        const int t = arow >> 7;
        arow = b * T_DIM + t;
    }
    const float* ag = A + (long)arow * K + skoff;
    const float* bg = W + (long)(n0 + srow) * K + skoff;
    float* adst = &As[srow * GS + skoff];
    float* bdst = &Bs[srow * GS + skoff];

    float acc[4][4][4];
#pragma unroll
    for (int i = 0; i < 4; i++)
#pragma unroll
        for (int j = 0; j < 4; j++)
#pragma unroll
            for (int v = 0; v < 4; v++) acc[i][j][v] = 0.f;

    float4 pa0 = *(const float4*)(ag);
    float4 pa1 = *(const float4*)(ag + 4);
    float4 pb0 = *(const float4*)(bg);
    float4 pb1 = *(const float4*)(bg + 4);

    for (int kc = 0; kc < K; kc += 16) {
        __syncthreads();
        st8tf_ilv(adst, pa0, pa1);
        st8tf_ilv(bdst, pb0, pb1);
        __syncthreads();
        if (kc + 16 < K) {
            pa0 = *(const float4*)(ag + kc + 16);
            pa1 = *(const float4*)(ag + kc + 20);
            pb0 = *(const float4*)(bg + kc + 16);
            pb1 = *(const float4*)(bg + kc + 20);
        }
#pragma unroll
        for (int ks = 0; ks < 16; ks += 8) {
            const int kb = ks + 2 * tig;
            float2 alo[4], ahi[4], bf[4];
#pragma unroll
            for (int i = 0; i < 4; i++) {
                const float* ap = &As[(wm + i * 16 + gid) * GS + kb];
                alo[i] = *(const float2*)ap;
                ahi[i] = *(const float2*)(ap + 8 * GS);
            }
#pragma unroll
            for (int j = 0; j < 4; j++)
                bf[j] = *(const float2*)&Bs[(wn + j * 8 + gid) * GS + kb];
#pragma unroll
            for (int i = 0; i < 4; i++)
#pragma unroll
                for (int j = 0; j < 4; j++)
                    mma8(acc[i][j][0], acc[i][j][1], acc[i][j][2], acc[i][j][3],
                         __float_as_uint(alo[i].x), __float_as_uint(ahi[i].x),
                         __float_as_uint(alo[i].y), __float_as_uint(ahi[i].y),
                         __float_as_uint(bf[j].x), __float_as_uint(bf[j].y));
        }
    }

#pragma unroll
    for (int j = 0; j < 4; j++) {
        const int n = n0 + wn + j * 8 + 2 * tig;
        float bz0 = bias1[n], bz1 = bias1[n + 1];
        if (bias2) { bz0 += bias2[n]; bz1 += bias2[n + 1]; }
#pragma unroll
        for (int i = 0; i < 4; i++) {
            const int m = m0 + wm + i * 16 + gid;
            float2 o1; o1.x = acc[i][j][0] + bz0; o1.y = acc[i][j][1] + bz1;
            float2 o2; o2.x = acc[i][j][2] + bz0; o2.y = acc[i][j][3] + bz1;
            *(float2*)(C + (long)m * N + n) = o1;
            *(float2*)(C + (long)(m + 8) * N + n) = o2;
        }
    }
}

// ============================================================================
// Grid-wide barrier (128 co-resident blocks).
// ============================================================================
__device__ __forceinline__ void grid_barrier()
{
    __threadfence();
    __syncthreads();
    if (threadIdx.x == 0) {
        const unsigned g = *(volatile unsigned int*)&g_bar_gen;
        const unsigned a = atomicAdd(&g_bar_cnt, 1u);
        if (a == NBLK - 1) {
            g_bar_cnt = 0;
            __threadfence();
            *(volatile unsigned int*)&g_bar_gen = g + 1u;
        } else {
            while (*(volatile unsigned int*)&g_bar_gen == g) __nanosleep(32);
        }
    }
    __syncthreads();
}

// ============================================================================
// Persistent LSTM layer, bf16 split tensor-core recurrence.
// Block (mb,bb): 16 h-cols x 32 batches; M=64 gate-rows, N=32, K=512.
// W split into bf16 hi/lo pair-planes in SMEM (once per layer). h split into
// hi/lo pair-planes per step (producers pre-pack into g_hpack).
// gates = pre + hi*hi + hi*lo + lo*hi  (residual ~2^-18).
// Warp w computes gate w via mma.m16n8k16; gates exchanged through SMEM.
// SMEM: 2*64*WP + 2*32*WP u32 + 64*GXS floats = 204 KB -> 1 block/SM.
// ============================================================================
__global__ __launch_bounds__(128, 1) void lstm_layer_kernel(
    const float* __restrict__ h0, const float* __restrict__ c0,
    const float* __restrict__ Whh, const float* __restrict__ gates,
    float* __restrict__ seq, uint32_t* __restrict__ hpack,
    float* __restrict__ hT, float* __restrict__ cT)
{
    extern __shared__ uint32_t smem[];
    uint32_t* ws_hi = smem;                        // [64][WP]
    uint32_t* ws_lo = ws_hi + 64 * WP;             // [64][WP]
    uint32_t* hs_hi = ws_lo + 64 * WP;             // [32][WP]
    uint32_t* hs_lo = hs_hi + 32 * WP;             // [32][WP]
    float*    gx    = (float*)(hs_lo + 32 * WP);   // [64][GXS]

    const int tid = threadIdx.x;
    const int lane = tid & 31;
    const int warp = tid >> 5;                     // = gate index
    const int fg = lane >> 2;                      // fragment group 0..7
    const int tq = lane & 3;                       // thread-in-group

    const int mb = blockIdx.x & 31;
    const int bb = blockIdx.x >> 5;
    const int m0 = mb * 16;
    const int b0 = bb * 32;

    // ---- stage W slice once: local row r = w*16+mli <-> Whh row w*HID+m0+mli
    for (int i = tid; i < 64 * 128; i += 128) {
        const int r = i >> 7;               // local row
        const int q = i & 127;              // float4 index (pairs 2q, 2q+1)
        const int w = r >> 4, mli = r & 15;
        const float4 v = *(const float4*)(Whh + (long)(w * HID + m0 + mli) * HID + (q << 2));
        uint32_t lo0, lo1;
        const uint32_t hi0 = split_pair(v.x, v.y, lo0);
        const uint32_t hi1 = split_pair(v.z, v.w, lo1);
        ws_hi[r * WP + 2 * q]     = hi0;
        ws_hi[r * WP + 2 * q + 1] = hi1;
        ws_lo[r * WP + 2 * q]     = lo0;
        ws_lo[r * WP + 2 * q + 1] = lo1;
    }

    // activation-phase roles: thread owns (m0+ml, batches b0+bq*4..+3)
    const int ml = tid & 15;
    const int bq = tid >> 4;
    const int m = m0 + ml;

    // h staging roles: thread stages quarter-row q of batch b
    const int sb = tid >> 2;            // 0..31 local batch
    const int sq = tid & 3;             // quarter (64 pairs each)

    float creg[4];
#pragma unroll
    for (int j = 0; j < 4; j++)
        creg[j] = c0[(long)(b0 + bq * 4 + j) * HID + m];

    for (int t = 0; t < T_DIM; t++) {
        // prefetch this step's precomputed gate contributions (global)
        const float* pre = gates + (long)t * B_DIM * G4;
        float pg[4][4];
#pragma unroll
        for (int g = 0; g < 4; g++)
#pragma unroll
            for (int j = 0; j < 4; j++)
                pg[g][j] = __ldcg(pre + (long)(b0 + bq * 4 + j) * G4 + (g << 9) + m);

        // ---- stage h(t-1) into hi/lo pair planes
        if (t == 0) {
            const float4* src = (const float4*)(h0 + (long)(b0 + sb) * HID + sq * 128);
#pragma unroll 4
            for (int i = 0; i < 32; i++) {
                const float4 v = __ldcg(src + i);
                const int p = sq * 64 + 2 * i;
                uint32_t lo0, lo1;
                const uint32_t hi0 = split_pair(v.x, v.y, lo0);
                const uint32_t hi1 = split_pair(v.z, v.w, lo1);
                hs_hi[sb * WP + p]     = hi0;
                hs_hi[sb * WP + p + 1] = hi1;
                hs_lo[sb * WP + p]     = lo0;
                hs_lo[sb * WP + p + 1] = lo1;
            }
        } else {
            const uint4* src = (const uint4*)(hpack + (long)(b0 + sb) * HID + sq * 128);
#pragma unroll 4
            for (int i = 0; i < 32; i++) {
                const uint4 u = __ldcg(src + i);
                const int p = sq * 64 + 2 * i;
                hs_hi[sb * WP + p]     = __byte_perm(u.x, u.y, 0x5410);
                hs_hi[sb * WP + p + 1] = __byte_perm(u.z, u.w, 0x5410);
                hs_lo[sb * WP + p]     = __byte_perm(u.x, u.y, 0x7632);
                hs_lo[sb * WP + p + 1] = __byte_perm(u.z, u.w, 0x7632);
            }
        }
        __syncthreads();   // planes ready (also covers W staging at t==0)

        // ---- mma: warp computes gate=warp for all 32 batches
        float acc[4][4];
#pragma unroll
        for (int j = 0; j < 4; j++)
#pragma unroll
            for (int v = 0; v < 4; v++) acc[j][v] = 0.f;

        const uint32_t* wh = ws_hi + (warp * 16) * WP;
        const uint32_t* wl = ws_lo + (warp * 16) * WP;

#pragma unroll 4
        for (int ks = 0; ks < 32; ks++) {
            const int pb = ks * 8 + tq;
            const uint32_t ah0 = wh[fg * WP + pb];
            const uint32_t ah1 = wh[(fg + 8) * WP + pb];
            const uint32_t ah2 = wh[fg * WP + pb + 4];
            const uint32_t ah3 = wh[(fg + 8) * WP + pb + 4];
            const uint32_t al0 = wl[fg * WP + pb];
            const uint32_t al1 = wl[(fg + 8) * WP + pb];
            const uint32_t al2 = wl[fg * WP + pb + 4];
            const uint32_t al3 = wl[(fg + 8) * WP + pb + 4];
#pragma unroll
            for (int j = 0; j < 4; j++) {
                const int bcol = 8 * j + fg;
                const uint32_t bh0 = hs_hi[bcol * WP + pb];
                const uint32_t bh1 = hs_hi[bcol * WP + pb + 4];
                const uint32_t bl0 = hs_lo[bcol * WP + pb];
                const uint32_t bl1 = hs_lo[bcol * WP + pb + 4];
                mma16bf(acc[j][0], acc[j][1], acc[j][2], acc[j][3],
                        ah0, ah1, ah2, ah3, bh0, bh1);
                mma16bf(acc[j][0], acc[j][1], acc[j][2], acc[j][3],
                        ah0, ah1, ah2, ah3, bl0, bl1);
                mma16bf(acc[j][0], acc[j][1], acc[j][2], acc[j][3],
                        al0, al1, al2, al3, bh0, bh1);
            }
        }

        // ---- exchange gate values through SMEM
#pragma unroll
        for (int j = 0; j < 4; j++) {
            float2 lo2; lo2.x = acc[j][0]; lo2.y = acc[j][1];
            float2 hi2; hi2.x = acc[j][2]; hi2.y = acc[j][3];
            *(float2*)&gx[(warp * 16 + fg) * GXS + 8 * j + 2 * tq] = lo2;
            *(float2*)&gx[(warp * 16 + fg + 8) * GXS + 8 * j + 2 * tq] = hi2;
        }
        __syncthreads();

        // ---- activations + state update
        float4 gv[4];
#pragma unroll
        for (int g = 0; g < 4; g++)
            gv[g] = *(const float4*)&gx[(g * 16 + ml) * GXS + bq * 4];

        float* hrow = seq + (long)t * STATE;
#pragma unroll
        for (int j = 0; j < 4; j++) {
            const int b = b0 + bq * 4 + j;
            const float gi = ((const float*)&gv[0])[j] + pg[0][j];
            const float gf = ((const float*)&gv[1])[j] + pg[1][j];
            const float gg = ((const float*)&gv[2])[j] + pg[2][j];
            const float go = ((const float*)&gv[3])[j] + pg[3][j];
            const float i_ = 1.f / (1.f + expf(-gi));
            const float f_ = 1.f / (1.f + expf(-gf));
            const float g_ = tanhf(gg);
            const float o_ = 1.f / (1.f + expf(-go));
            const float c = f_ * creg[j] + i_ * g_;
            creg[j] = c;
            const float h = o_ * tanhf(c);
            hrow[(long)b * HID + m] = h;
            hpack[(long)b * HID + m] = hpk(h);
            if (t == T_DIM - 1) {
                hT[(long)b * HID + m] = h;
                cT[(long)b * HID + m] = c;
            }
        }

        grid_barrier();          // publish h(t) + hpack(t) before step t+1
    }
}

// ============================================================================
// LayerNorm + (t,b)->(b,t) transpose (unchanged).
// ============================================================================
__global__ __launch_bounds__(256) void ln_out_kernel(
    const float* __restrict__ X, const float* __restrict__ gamma,
    const float* __restrict__ beta, float* __restrict__ out)
{
    const int row = blockIdx.x;
    const float* x = X + (long)row * OUT_DIM;
    const int tid = threadIdx.x;

    const float v0 = x[tid];
    const float v1 = x[tid + 256];
    const float v2 = x[tid + 512];

    __shared__ float red[8];
    __shared__ float s_mu, s_rs;

    float s = v0 + v1 + v2;
#pragma unroll
    for (int o = 16; o > 0; o >>= 1) s += __shfl_down_sync(0xffffffffu, s, o);
    if ((tid & 31) == 0) red[tid >> 5] = s;
    __syncthreads();
    if (tid == 0) {
        float tot = 0.f;
#pragma unroll
        for (int i = 0; i < 8; i++) tot += red[i];
        s_mu = tot * (1.f / OUT_DIM);
    }
    __syncthreads();
    const float mu = s_mu;
    const float d0 = v0 - mu, d1 = v1 - mu, d2 = v2 - mu;

    float q = d0 * d0 + d1 * d1 + d2 * d2;
#pragma unroll
    for (int o = 16; o > 0; o >>= 1) q += __shfl_down_sync(0xffffffffu, q, o);
    if ((tid & 31) == 0) red[tid >> 5] = q;
    __syncthreads();
    if (tid == 0) {
        float tot = 0.f;
#pragma unroll
        for (int i = 0; i < 8; i++) tot += red[i];
        s_rs = rsqrtf(tot * (1.f / OUT_DIM) + 1e-5f);
    }
    __syncthreads();
    const float rs = s_rs;

    const int b = row & (B_DIM - 1);
    const int t = row >> 7;
    float* o = out + (long)(b * T_DIM + t) * OUT_DIM;
    o[tid]       = d0 * rs * gamma[tid]       + beta[tid];
    o[tid + 256] = d1 * rs * gamma[tid + 256] + beta[tid + 256];
    o[tid + 512] = d2 * rs * gamma[tid + 512] + beta[tid + 512];
}

// ============================================================================
extern "C" void kernel_launch(void* const* d_in, const int* in_sizes, int n_in,
                              void* d_out, int out_size)
{
    const float* x     = (const float*)d_in[0];
    const float* h0    = (const float*)d_in[1];
    const float* c0    = (const float*)d_in[2];
    const float* W_in  = (const float*)d_in[3];
    const float* b_in  = (const float*)d_in[4];
    const float* W_ih  = (const float*)d_in[5];
    const float* W_hh  = (const float*)d_in[6];
    const float* b_ih  = (const float*)d_in[7];
    const float* b_hh  = (const float*)d_in[8];
    const float* W_out = (const float*)d_in[9];
    const float* b_out = (const float*)d_in[10];
    const float* ln_g  = (const float*)d_in[11];
    const float* ln_b  = (const float*)d_in[12];
    float* out = (float*)d_out;

    float *seqA, *seqB, *gates, *outp;
    uint32_t* hpack;
    cudaGetSymbolAddress((void**)&seqA, g_seqA);
    cudaGetSymbolAddress((void**)&seqB, g_seqB);
    cudaGetSymbolAddress((void**)&gates, g_gates);
    cudaGetSymbolAddress((void**)&outp, g_outp);
    cudaGetSymbolAddress((void**)&hpack, g_hpack);

    const int lstm_smem = (2 * 64 * WP + 2 * 32 * WP + 64 * GXS) * 4;  // ~204 KB
    cudaFuncSetAttribute(lstm_layer_kernel,
                         cudaFuncAttributeMaxDynamicSharedMemorySize, lstm_smem);

    const long OUT_ELEMS = (long)B_DIM * T_DIM * OUT_DIM;

    // 1) input projection with (b,t)->(t,b) transpose (tf32 TC)
    gemm_tf32<<<dim3(ROWS / 128, HID / 128), 256>>>(x, W_in, b_in, nullptr, seqA,
                                                    INP_DIM, HID, 1);

    for (int l = 0; l < NL; l++) {
        const float* in = (l & 1) ? seqB : seqA;
        float* outSeq   = (l & 1) ? seqA : seqB;

        // 2a) parallel: gates = in @ W_ih[l]^T + b_ih[l] + b_hh[l] (tf32 TC)
        gemm_tf32<<<dim3(ROWS / 128, G4 / 128), 256>>>(
            in, W_ih + (long)l * G4 * HID, b_ih + l * G4, b_hh + l * G4,
            gates, HID, G4, 0);

        // 2b) serial recurrence: one persistent launch, bf16 split tensor cores
        lstm_layer_kernel<<<NBLK, 128, lstm_smem>>>(
            h0 + (long)l * STATE, c0 + (long)l * STATE,
            W_hh + (long)l * G4 * HID, gates, outSeq, hpack,
            out + OUT_ELEMS + (long)l * STATE,
            out + OUT_ELEMS + (long)NL * STATE + (long)l * STATE);
    }

    // 3) output projection (tf32 TC)
    gemm_tf32<<<dim3(ROWS / 128, OUT_DIM / 128), 256>>>(seqA, W_out, b_out, nullptr,
                                                        outp, HID, OUT_DIM, 0);

    // 4) layernorm + transpose into d_out
    ln_out_kernel<<<ROWS, 256>>>(outp, ln_g, ln_b, out);
}

// round 9
// speedup vs baseline: 2.1178x; 1.1792x over previous
#include <cuda_runtime.h>
#include <cuda_bf16.h>
#include <math.h>
#include <stdint.h>

#define T_DIM 256
#define B_DIM 128
#define INP_DIM 768
#define HID 512
#define OUT_DIM 768
#define NL 4
#define G4 (4 * HID)            // 2048
#define ROWS (T_DIM * B_DIM)    // 32768
#define STATE (B_DIM * HID)     // 65536

#define NBLK 128                // persistent recurrence grid (1 block/SM)
#define GS 24                   // ff-gemm SMEM row stride (floats)

// recurrence chunked SMEM: per (row, ks) 4 x 16B chunks; row stride in u32.
// 528*4 = 2112 B, 2112 mod 128 = 64 -> adjacent rows alternate bank halves
// -> every LDS.128 phase (8 lanes) is conflict-free.
#define RSTR 528
#define GXS 36                  // gate-exchange stride (floats)

// ---------------- scratch (static device globals: no allocation) ----------------
__device__ float g_seqA[ROWS * HID];
__device__ float g_seqB[ROWS * HID];
__device__ float g_gates[ROWS * G4];
__device__ float g_outp[ROWS * OUT_DIM];
__device__ uint32_t g_hpack[STATE];      // h packed as (bf16 hi | bf16 lo << 16)

__device__ unsigned int g_bar_cnt = 0;
__device__ unsigned int g_bar_gen = 0;

// ---------------- tf32 helpers (FF GEMM) ----------------
__device__ __forceinline__ uint32_t f2tf(float f) {
    uint32_t u;
    asm("cvt.rna.tf32.f32 %0, %1;" : "=r"(u) : "f"(f));
    return u;
}
__device__ __forceinline__ void st8tf_ilv(float* p, float4 v0, float4 v1) {
    float4 t0, t1;
    t0.x = __uint_as_float(f2tf(v0.x));
    t0.y = __uint_as_float(f2tf(v1.x));
    t0.z = __uint_as_float(f2tf(v0.y));
    t0.w = __uint_as_float(f2tf(v1.y));
    t1.x = __uint_as_float(f2tf(v0.z));
    t1.y = __uint_as_float(f2tf(v1.z));
    t1.z = __uint_as_float(f2tf(v0.w));
    t1.w = __uint_as_float(f2tf(v1.w));
    *(float4*)p = t0;
    *(float4*)(p + 4) = t1;
}
__device__ __forceinline__ void mma8(float& c0, float& c1, float& c2, float& c3,
                                     uint32_t a0, uint32_t a1, uint32_t a2, uint32_t a3,
                                     uint32_t b0, uint32_t b1) {
    asm volatile("mma.sync.aligned.m16n8k8.row.col.f32.tf32.tf32.f32 "
                 "{%0,%1,%2,%3}, {%4,%5,%6,%7}, {%8,%9}, {%0,%1,%2,%3};"
                 : "+f"(c0), "+f"(c1), "+f"(c2), "+f"(c3)
                 : "r"(a0), "r"(a1), "r"(a2), "r"(a3), "r"(b0), "r"(b1));
}

// ---------------- bf16 helpers (recurrence) ----------------
__device__ __forceinline__ void mma16bf(float& c0, float& c1, float& c2, float& c3,
                                        uint32_t a0, uint32_t a1, uint32_t a2, uint32_t a3,
                                        uint32_t b0, uint32_t b1) {
    asm volatile("mma.sync.aligned.m16n8k16.row.col.f32.bf16.bf16.f32 "
                 "{%0,%1,%2,%3}, {%4,%5,%6,%7}, {%8,%9}, {%0,%1,%2,%3};"
                 : "+f"(c0), "+f"(c1), "+f"(c2), "+f"(c3)
                 : "r"(a0), "r"(a1), "r"(a2), "r"(a3), "r"(b0), "r"(b1));
}
__device__ __forceinline__ uint32_t split_pair(float a, float b, uint32_t& lo) {
    __nv_bfloat16 ah = __float2bfloat16_rn(a);
    __nv_bfloat16 bh = __float2bfloat16_rn(b);
    __nv_bfloat16 al = __float2bfloat16_rn(a - __bfloat162float(ah));
    __nv_bfloat16 bl = __float2bfloat16_rn(b - __bfloat162float(bh));
    lo = (uint32_t)__bfloat16_as_ushort(al) | ((uint32_t)__bfloat16_as_ushort(bl) << 16);
    return (uint32_t)__bfloat16_as_ushort(ah) | ((uint32_t)__bfloat16_as_ushort(bh) << 16);
}
__device__ __forceinline__ uint32_t hpk(float h) {
    __nv_bfloat16 hi = __float2bfloat16_rn(h);
    __nv_bfloat16 lo = __float2bfloat16_rn(h - __bfloat162float(hi));
    return (uint32_t)__bfloat16_as_ushort(hi) | ((uint32_t)__bfloat16_as_ushort(lo) << 16);
}

// Build 4 16B chunks {hi(tq),hi(tq+4),lo(tq),lo(tq+4)} from 16 fp32 values.
__device__ __forceinline__ void make_chunks_f32(const float* v, uint4* out) {
    uint32_t hi[8], lo[8];
#pragma unroll
    for (int p = 0; p < 8; p++) hi[p] = split_pair(v[2 * p], v[2 * p + 1], lo[p]);
#pragma unroll
    for (int tq = 0; tq < 4; tq++) {
        out[tq].x = hi[tq];
        out[tq].y = hi[tq + 4];
        out[tq].z = lo[tq];
        out[tq].w = lo[tq + 4];
    }
}
// Same from 16 hpack-packed u32 values (hi|lo<<16).
__device__ __forceinline__ void make_chunks_pk(const uint32_t* w, uint4* out) {
#pragma unroll
    for (int tq = 0; tq < 4; tq++) {
        const uint32_t a = w[2 * tq],     b = w[2 * tq + 1];
        const uint32_t c = w[2 * tq + 8], d = w[2 * tq + 9];
        out[tq].x = __byte_perm(a, b, 0x5410);
        out[tq].y = __byte_perm(c, d, 0x5410);
        out[tq].z = __byte_perm(a, b, 0x7632);
        out[tq].w = __byte_perm(c, d, 0x7632);
    }
}

// ============================================================================
// tf32 tensor-core GEMM, 2-stage SMEM double buffering (1 sync per k-chunk).
// ============================================================================
__global__ __launch_bounds__(256) void gemm_tf32(
    const float* __restrict__ A, const float* __restrict__ W,
    const float* __restrict__ bias1, const float* __restrict__ bias2,
    float* __restrict__ C, int K, int N, int xremap)
{
    __shared__ __align__(16) float As[2][128 * GS];
    __shared__ __align__(16) float Bs[2][128 * GS];

    const int m0 = blockIdx.x * 128;
    const int n0 = blockIdx.y * 128;
    const int tid = threadIdx.x;
    const int lane = tid & 31;
    const int warp = tid >> 5;
    const int gid = lane >> 2;
    const int tig = lane & 3;
    const int wm = (warp >> 2) * 64;
    const int wn = (warp & 3) * 32;

    const int srow = tid >> 1;
    const int skoff = (tid & 1) * 8;
    int arow = m0 + srow;
    if (xremap) {
        const int b = arow & (B_DIM - 1);
        const int t = arow >> 7;
        arow = b * T_DIM + t;
    }
    const float* ag = A + (long)arow * K + skoff;
    const float* bg = W + (long)(n0 + srow) * K + skoff;
    const int soff = srow * GS + skoff;

    float acc[4][4][4];
#pragma unroll
    for (int i = 0; i < 4; i++)
#pragma unroll
        for (int j = 0; j < 4; j++)
#pragma unroll
            for (int v = 0; v < 4; v++) acc[i][j][v] = 0.f;

    // prologue: stage chunk 0
    {
        float4 pa0 = *(const float4*)(ag);
        float4 pa1 = *(const float4*)(ag + 4);
        float4 pb0 = *(const float4*)(bg);
        float4 pb1 = *(const float4*)(bg + 4);
        st8tf_ilv(&As[0][soff], pa0, pa1);
        st8tf_ilv(&Bs[0][soff], pb0, pb1);
    }
    __syncthreads();

    const int nch = K >> 4;
    for (int c = 0; c < nch; c++) {
        const int s = c & 1;
        const bool more = (c + 1 < nch);
        float4 na0, na1, nb0, nb1;
        if (more) {
            const int ko = (c + 1) << 4;
            na0 = *(const float4*)(ag + ko);
            na1 = *(const float4*)(ag + ko + 4);
            nb0 = *(const float4*)(bg + ko);
            nb1 = *(const float4*)(bg + ko + 4);
        }
#pragma unroll
        for (int ks = 0; ks < 16; ks += 8) {
            const int kb = ks + 2 * tig;
            float2 alo[4], ahi[4], bf[4];
#pragma unroll
            for (int i = 0; i < 4; i++) {
                const float* ap = &As[s][(wm + i * 16 + gid) * GS + kb];
                alo[i] = *(const float2*)ap;
                ahi[i] = *(const float2*)(ap + 8 * GS);
            }
#pragma unroll
            for (int j = 0; j < 4; j++)
                bf[j] = *(const float2*)&Bs[s][(wn + j * 8 + gid) * GS + kb];
#pragma unroll
            for (int i = 0; i < 4; i++)
#pragma unroll
                for (int j = 0; j < 4; j++)
                    mma8(acc[i][j][0], acc[i][j][1], acc[i][j][2], acc[i][j][3],
                         __float_as_uint(alo[i].x), __float_as_uint(ahi[i].x),
                         __float_as_uint(alo[i].y), __float_as_uint(ahi[i].y),
                         __float_as_uint(bf[j].x), __float_as_uint(bf[j].y));
        }
        if (more) {
            st8tf_ilv(&As[s ^ 1][soff], na0, na1);
            st8tf_ilv(&Bs[s ^ 1][soff], nb0, nb1);
        }
        __syncthreads();
    }

#pragma unroll
    for (int j = 0; j < 4; j++) {
        const int n = n0 + wn + j * 8 + 2 * tig;
        float bz0 = bias1[n], bz1 = bias1[n + 1];
        if (bias2) { bz0 += bias2[n]; bz1 += bias2[n + 1]; }
#pragma unroll
        for (int i = 0; i < 4; i++) {
            const int m = m0 + wm + i * 16 + gid;
            float2 o1; o1.x = acc[i][j][0] + bz0; o1.y = acc[i][j][1] + bz1;
            float2 o2; o2.x = acc[i][j][2] + bz0; o2.y = acc[i][j][3] + bz1;
            *(float2*)(C + (long)m * N + n) = o1;
            *(float2*)(C + (long)(m + 8) * N + n) = o2;
        }
    }
}

// ============================================================================
// Grid-wide barrier (128 co-resident blocks).
// ============================================================================
__device__ __forceinline__ void grid_barrier()
{
    __threadfence();
    __syncthreads();
    if (threadIdx.x == 0) {
        const unsigned g = *(volatile unsigned int*)&g_bar_gen;
        const unsigned a = atomicAdd(&g_bar_cnt, 1u);
        if (a == NBLK - 1) {
            g_bar_cnt = 0;
            __threadfence();
            *(volatile unsigned int*)&g_bar_gen = g + 1u;
        } else {
            while (*(volatile unsigned int*)&g_bar_gen == g) __nanosleep(32);
        }
    }
    __syncthreads();
}

// ============================================================================
// Persistent LSTM layer, bf16-split tensor cores, 256 threads (8 warps).
// Warp w: gate g = w&3, k-half kh = w>>2 (2 warps/SMSP -> latency hiding).
// SMEM chunk layout: per (row, ks-chunk, tq) one 16B chunk
//   {hi(kpair tq), hi(kpair tq+4), lo(tq), lo(tq+4)}
// -> ONE LDS.128 per fragment covering both split planes.
// gates = pre + Whi*hhi + Whi*hlo + Wlo*hhi. Partial sums per k-half go to two
// gx planes, summed in the activation phase.
// SMEM: 64*RSTR + 32*RSTR u32 + 2*64*GXS floats = 216 KB -> 1 block/SM.
// ============================================================================
__global__ __launch_bounds__(256, 1) void lstm_layer_kernel(
    const float* __restrict__ h0, const float* __restrict__ c0,
    const float* __restrict__ Whh, const float* __restrict__ gates,
    float* __restrict__ seq, uint32_t* __restrict__ hpack,
    float* __restrict__ hT, float* __restrict__ cT)
{
    extern __shared__ uint32_t smem[];
    uint32_t* ws = smem;                       // [64][RSTR]
    uint32_t* hs = ws + 64 * RSTR;             // [32][RSTR]
    float*    gx = (float*)(hs + 32 * RSTR);   // [2][64][GXS]

    const int tid = threadIdx.x;
    const int lane = tid & 31;
    const int warp = tid >> 5;
    const int g = warp & 3;                    // gate
    const int kh = warp >> 2;                  // k-half
    const int fg = lane >> 2;                  // fragment group 0..7
    const int tq = lane & 3;

    const int mb = blockIdx.x & 31;
    const int bb = blockIdx.x >> 5;
    const int m0 = mb * 16;
    const int b0 = bb * 32;

    // ---- stage W slice once: cell = (local row r, ks); 2048 cells / 256 thr
#pragma unroll
    for (int i = 0; i < 8; i++) {
        const int cell = tid + 256 * i;
        const int r = cell >> 5;
        const int ks = cell & 31;
        const int wg = r >> 4, mli = r & 15;
        const float* wrow = Whh + (long)(wg * HID + m0 + mli) * HID + ks * 16;
        float v[16];
#pragma unroll
        for (int q = 0; q < 4; q++) *(float4*)(v + 4 * q) = *(const float4*)(wrow + 4 * q);
        uint4 ck[4];
        make_chunks_f32(v, ck);
        uint32_t* dst = ws + r * RSTR + ks * 16;
#pragma unroll
        for (int q = 0; q < 4; q++) *(uint4*)(dst + 4 * q) = ck[q];
    }

    // activation roles: thread = (ml 0..15, bh 0..15) -> 2 batches
    const int ml = tid & 15;
    const int bh = tid >> 4;
    const int lb0 = 2 * bh;
    const int m = m0 + ml;

    float creg[2];
#pragma unroll
    for (int j = 0; j < 2; j++)
        creg[j] = c0[(long)(b0 + lb0 + j) * HID + m];

    for (int t = 0; t < T_DIM; t++) {
        // prefetch this step's precomputed gate contributions
        const float* pre = gates + (long)t * B_DIM * G4;
        float pg[4][2];
#pragma unroll
        for (int gg = 0; gg < 4; gg++)
#pragma unroll
            for (int j = 0; j < 2; j++)
                pg[gg][j] = __ldcg(pre + (long)(b0 + lb0 + j) * G4 + (gg << 9) + m);

        // ---- stage h(t-1): cell = (sb, ks); 1024 cells / 256 threads
        if (t == 0) {
#pragma unroll
            for (int i = 0; i < 4; i++) {
                const int cell = tid + 256 * i;
                const int sb = cell >> 5;
                const int ks = cell & 31;
                const float* hrow = h0 + (long)(b0 + sb) * HID + ks * 16;
                float v[16];
#pragma unroll
                for (int q = 0; q < 4; q++) *(float4*)(v + 4 * q) = __ldcg((const float4*)(hrow + 4 * q));
                uint4 ck[4];
                make_chunks_f32(v, ck);
                uint32_t* dst = hs + sb * RSTR + ks * 16;
#pragma unroll
                for (int q = 0; q < 4; q++) *(uint4*)(dst + 4 * q) = ck[q];
            }
        } else {
#pragma unroll
            for (int i = 0; i < 4; i++) {
                const int cell = tid + 256 * i;
                const int sb = cell >> 5;
                const int ks = cell & 31;
                const uint32_t* hrow = hpack + (long)(b0 + sb) * HID + ks * 16;
                uint32_t u[16];
#pragma unroll
                for (int q = 0; q < 4; q++) *(uint4*)(u + 4 * q) = __ldcg((const uint4*)(hrow + 4 * q));
                uint4 ck[4];
                make_chunks_pk(u, ck);
                uint32_t* dst = hs + sb * RSTR + ks * 16;
#pragma unroll
                for (int q = 0; q < 4; q++) *(uint4*)(dst + 4 * q) = ck[q];
            }
        }
        __syncthreads();   // hs (and ws at t==0) ready

        // ---- mma: warp computes gate g, k-half kh, all 32 batches
        float acc[4][4];
#pragma unroll
        for (int j = 0; j < 4; j++)
#pragma unroll
            for (int v = 0; v < 4; v++) acc[j][v] = 0.f;

        const uint32_t* wbase = ws + (g * 16) * RSTR;
        const int ks0 = kh * 16;
#pragma unroll 4
        for (int ks = ks0; ks < ks0 + 16; ks++) {
            const int off = ks * 16 + tq * 4;
            const uint4 A0 = *(const uint4*)(wbase + fg * RSTR + off);
            const uint4 A1 = *(const uint4*)(wbase + (fg + 8) * RSTR + off);
#pragma unroll
            for (int j = 0; j < 4; j++) {
                const uint4 Bv = *(const uint4*)(hs + (8 * j + fg) * RSTR + off);
                mma16bf(acc[j][0], acc[j][1], acc[j][2], acc[j][3],
                        A0.x, A1.x, A0.y, A1.y, Bv.x, Bv.y);   // hi*hi
                mma16bf(acc[j][0], acc[j][1], acc[j][2], acc[j][3],
                        A0.x, A1.x, A0.y, A1.y, Bv.z, Bv.w);   // hi*lo
                mma16bf(acc[j][0], acc[j][1], acc[j][2], acc[j][3],
                        A0.z, A1.z, A0.w, A1.w, Bv.x, Bv.y);   // lo*hi
            }
        }

        // ---- write partial gates to this k-half's exchange plane
        float* gxp = gx + kh * (64 * GXS);
#pragma unroll
        for (int j = 0; j < 4; j++) {
            float2 lo2; lo2.x = acc[j][0]; lo2.y = acc[j][1];
            float2 hi2; hi2.x = acc[j][2]; hi2.y = acc[j][3];
            *(float2*)&gxp[(g * 16 + fg) * GXS + 8 * j + 2 * tq] = lo2;
            *(float2*)&gxp[(g * 16 + fg + 8) * GXS + 8 * j + 2 * tq] = hi2;
        }
        __syncthreads();

        // ---- activations: sum k-halves, update state, write h
        float gate[4][2];
#pragma unroll
        for (int gg = 0; gg < 4; gg++) {
            const float2 p0 = *(const float2*)&gx[(gg * 16 + ml) * GXS + lb0];
            const float2 p1 = *(const float2*)&gx[64 * GXS + (gg * 16 + ml) * GXS + lb0];
            gate[gg][0] = p0.x + p1.x;
            gate[gg][1] = p0.y + p1.y;
        }

        float* hrow = seq + (long)t * STATE;
#pragma unroll
        for (int j = 0; j < 2; j++) {
            const int b = b0 + lb0 + j;
            const float gi = gate[0][j] + pg[0][j];
            const float gf = gate[1][j] + pg[1][j];
            const float gg = gate[2][j] + pg[2][j];
            const float go = gate[3][j] + pg[3][j];
            const float i_ = 1.f / (1.f + expf(-gi));
            const float f_ = 1.f / (1.f + expf(-gf));
            const float g_ = tanhf(gg);
            const float o_ = 1.f / (1.f + expf(-go));
            const float c = f_ * creg[j] + i_ * g_;
            creg[j] = c;
            const float h = o_ * tanhf(c);
            hrow[(long)b * HID + m] = h;
            hpack[(long)b * HID + m] = hpk(h);
            if (t == T_DIM - 1) {
                hT[(long)b * HID + m] = h;
                cT[(long)b * HID + m] = c;
            }
        }

        grid_barrier();    // publish h(t)/hpack(t); also guards hs reuse
    }
}

// ============================================================================
// LayerNorm + (t,b)->(b,t) transpose (unchanged).
// ============================================================================
__global__ __launch_bounds__(256) void ln_out_kernel(
    const float* __restrict__ X, const float* __restrict__ gamma,
    const float* __restrict__ beta, float* __restrict__ out)
{
    const int row = blockIdx.x;
    const float* x = X + (long)row * OUT_DIM;
    const int tid = threadIdx.x;

    const float v0 = x[tid];
    const float v1 = x[tid + 256];
    const float v2 = x[tid + 512];

    __shared__ float red[8];
    __shared__ float s_mu, s_rs;

    float s = v0 + v1 + v2;
#pragma unroll
    for (int o = 16; o > 0; o >>= 1) s += __shfl_down_sync(0xffffffffu, s, o);
    if ((tid & 31) == 0) red[tid >> 5] = s;
    __syncthreads();
    if (tid == 0) {
        float tot = 0.f;
#pragma unroll
        for (int i = 0; i < 8; i++) tot += red[i];
        s_mu = tot * (1.f / OUT_DIM);
    }
    __syncthreads();
    const float mu = s_mu;
    const float d0 = v0 - mu, d1 = v1 - mu, d2 = v2 - mu;

    float q = d0 * d0 + d1 * d1 + d2 * d2;
#pragma unroll
    for (int o = 16; o > 0; o >>= 1) q += __shfl_down_sync(0xffffffffu, q, o);
    if ((tid & 31) == 0) red[tid >> 5] = q;
    __syncthreads();
    if (tid == 0) {
        float tot = 0.f;
#pragma unroll
        for (int i = 0; i < 8; i++) tot += red[i];
        s_rs = rsqrtf(tot * (1.f / OUT_DIM) + 1e-5f);
    }
    __syncthreads();
    const float rs = s_rs;

    const int b = row & (B_DIM - 1);
    const int t = row >> 7;
    float* o = out + (long)(b * T_DIM + t) * OUT_DIM;
    o[tid]       = d0 * rs * gamma[tid]       + beta[tid];
    o[tid + 256] = d1 * rs * gamma[tid + 256] + beta[tid + 256];
    o[tid + 512] = d2 * rs * gamma[tid + 512] + beta[tid + 512];
}

// ============================================================================
extern "C" void kernel_launch(void* const* d_in, const int* in_sizes, int n_in,
                              void* d_out, int out_size)
{
    const float* x     = (const float*)d_in[0];
    const float* h0    = (const float*)d_in[1];
    const float* c0    = (const float*)d_in[2];
    const float* W_in  = (const float*)d_in[3];
    const float* b_in  = (const float*)d_in[4];
    const float* W_ih  = (const float*)d_in[5];
    const float* W_hh  = (const float*)d_in[6];
    const float* b_ih  = (const float*)d_in[7];
    const float* b_hh  = (const float*)d_in[8];
    const float* W_out = (const float*)d_in[9];
    const float* b_out = (const float*)d_in[10];
    const float* ln_g  = (const float*)d_in[11];
    const float* ln_b  = (const float*)d_in[12];
    float* out = (float*)d_out;

    float *seqA, *seqB, *gates, *outp;
    uint32_t* hpack;
    cudaGetSymbolAddress((void**)&seqA, g_seqA);
    cudaGetSymbolAddress((void**)&seqB, g_seqB);
    cudaGetSymbolAddress((void**)&gates, g_gates);
    cudaGetSymbolAddress((void**)&outp, g_outp);
    cudaGetSymbolAddress((void**)&hpack, g_hpack);

    const int lstm_smem = (64 * RSTR + 32 * RSTR) * 4 + 2 * 64 * GXS * 4;  // ~216 KB
    cudaFuncSetAttribute(lstm_layer_kernel,
                         cudaFuncAttributeMaxDynamicSharedMemorySize, lstm_smem);

    const long OUT_ELEMS = (long)B_DIM * T_DIM * OUT_DIM;

    // 1) input projection with (b,t)->(t,b) transpose (tf32 TC)
    gemm_tf32<<<dim3(ROWS / 128, HID / 128), 256>>>(x, W_in, b_in, nullptr, seqA,
                                                    INP_DIM, HID, 1);

    for (int l = 0; l < NL; l++) {
        const float* in = (l & 1) ? seqB : seqA;
        float* outSeq   = (l & 1) ? seqA : seqB;

        // 2a) parallel: gates = in @ W_ih[l]^T + b_ih[l] + b_hh[l] (tf32 TC)
        gemm_tf32<<<dim3(ROWS / 128, G4 / 128), 256>>>(
            in, W_ih + (long)l * G4 * HID, b_ih + l * G4, b_hh + l * G4,
            gates, HID, G4, 0);

        // 2b) serial recurrence: one persistent launch, bf16-split tensor cores
        lstm_layer_kernel<<<NBLK, 256, lstm_smem>>>(
            h0 + (long)l * STATE, c0 + (long)l * STATE,
            W_hh + (long)l * G4 * HID, gates, outSeq, hpack,
            out + OUT_ELEMS + (long)l * STATE,
            out + OUT_ELEMS + (long)NL * STATE + (long)l * STATE);
    }

    // 3) output projection (tf32 TC)
    gemm_tf32<<<dim3(ROWS / 128, OUT_DIM / 128), 256>>>(seqA, W_out, b_out, nullptr,
                                                        outp, HID, OUT_DIM, 0);

    // 4) layernorm + transpose into d_out
    ln_out_kernel<<<ROWS, 256>>>(outp, ln_g, ln_b, out);
}

// round 10
// speedup vs baseline: 2.2972x; 1.0847x over previous
#include <cuda_runtime.h>
#include <cuda_bf16.h>
#include <math.h>
#include <stdint.h>

#define T_DIM 256
#define B_DIM 128
#define INP_DIM 768
#define HID 512
#define OUT_DIM 768
#define NL 4
#define G4 (4 * HID)            // 2048
#define ROWS (T_DIM * B_DIM)    // 32768
#define STATE (B_DIM * HID)     // 65536

#define NBLK 128                // persistent recurrence grid (<= SM count)
#define GS 24                   // ff-gemm SMEM row stride (floats)

// recurrence chunked SMEM row stride (u32). 528*4 = 2112 B, 2112 mod 128 = 64
// -> every LDS.128 phase (8 lanes) conflict-free.
#define RSTR 528
#define GXS 36                  // gate-exchange stride (floats)

// ---------------- scratch (static device globals: no allocation) ----------------
__device__ float g_seqA[ROWS * HID];
__device__ float g_seqB[ROWS * HID];
__device__ float g_gates[ROWS * G4];
__device__ float g_outp[ROWS * OUT_DIM];
__device__ uint32_t g_hpack[STATE];      // h packed as (bf16 hi | bf16 lo << 16)

__device__ unsigned int g_bar_cnt = 0;
__device__ unsigned int g_bar_gen = 0;

// ---------------- tf32 helpers (FF GEMM) ----------------
__device__ __forceinline__ uint32_t f2tf(float f) {
    uint32_t u;
    asm("cvt.rna.tf32.f32 %0, %1;" : "=r"(u) : "f"(f));
    return u;
}
__device__ __forceinline__ void st8tf_ilv(float* p, float4 v0, float4 v1) {
    float4 t0, t1;
    t0.x = __uint_as_float(f2tf(v0.x));
    t0.y = __uint_as_float(f2tf(v1.x));
    t0.z = __uint_as_float(f2tf(v0.y));
    t0.w = __uint_as_float(f2tf(v1.y));
    t1.x = __uint_as_float(f2tf(v0.z));
    t1.y = __uint_as_float(f2tf(v1.z));
    t1.z = __uint_as_float(f2tf(v0.w));
    t1.w = __uint_as_float(f2tf(v1.w));
    *(float4*)p = t0;
    *(float4*)(p + 4) = t1;
}
__device__ __forceinline__ void mma8(float& c0, float& c1, float& c2, float& c3,
                                     uint32_t a0, uint32_t a1, uint32_t a2, uint32_t a3,
                                     uint32_t b0, uint32_t b1) {
    asm volatile("mma.sync.aligned.m16n8k8.row.col.f32.tf32.tf32.f32 "
                 "{%0,%1,%2,%3}, {%4,%5,%6,%7}, {%8,%9}, {%0,%1,%2,%3};"
                 : "+f"(c0), "+f"(c1), "+f"(c2), "+f"(c3)
                 : "r"(a0), "r"(a1), "r"(a2), "r"(a3), "r"(b0), "r"(b1));
}

// ---------------- bf16 helpers (recurrence) ----------------
__device__ __forceinline__ void mma16bf(float& c0, float& c1, float& c2, float& c3,
                                        uint32_t a0, uint32_t a1, uint32_t a2, uint32_t a3,
                                        uint32_t b0, uint32_t b1) {
    asm volatile("mma.sync.aligned.m16n8k16.row.col.f32.bf16.bf16.f32 "
                 "{%0,%1,%2,%3}, {%4,%5,%6,%7}, {%8,%9}, {%0,%1,%2,%3};"
                 : "+f"(c0), "+f"(c1), "+f"(c2), "+f"(c3)
                 : "r"(a0), "r"(a1), "r"(a2), "r"(a3), "r"(b0), "r"(b1));
}
__device__ __forceinline__ uint32_t split_pair(float a, float b, uint32_t& lo) {
    __nv_bfloat16 ah = __float2bfloat16_rn(a);
    __nv_bfloat16 bh = __float2bfloat16_rn(b);
    __nv_bfloat16 al = __float2bfloat16_rn(a - __bfloat162float(ah));
    __nv_bfloat16 bl = __float2bfloat16_rn(b - __bfloat162float(bh));
    lo = (uint32_t)__bfloat16_as_ushort(al) | ((uint32_t)__bfloat16_as_ushort(bl) << 16);
    return (uint32_t)__bfloat16_as_ushort(ah) | ((uint32_t)__bfloat16_as_ushort(bh) << 16);
}
__device__ __forceinline__ uint32_t hpk(float h) {
    __nv_bfloat16 hi = __float2bfloat16_rn(h);
    __nv_bfloat16 lo = __float2bfloat16_rn(h - __bfloat162float(hi));
    return (uint32_t)__bfloat16_as_ushort(hi) | ((uint32_t)__bfloat16_as_ushort(lo) << 16);
}

// Build 4 16B chunks {hi(tq),hi(tq+4),lo(tq),lo(tq+4)} from 16 fp32 values.
__device__ __forceinline__ void make_chunks_f32(const float* v, uint4* out) {
    uint32_t hi[8], lo[8];
#pragma unroll
    for (int p = 0; p < 8; p++) hi[p] = split_pair(v[2 * p], v[2 * p + 1], lo[p]);
#pragma unroll
    for (int tq = 0; tq < 4; tq++) {
        out[tq].x = hi[tq];
        out[tq].y = hi[tq + 4];
        out[tq].z = lo[tq];
        out[tq].w = lo[tq + 4];
    }
}
// Same from 16 hpack-packed u32 values (hi|lo<<16).
__device__ __forceinline__ void make_chunks_pk(const uint32_t* w, uint4* out) {
#pragma unroll
    for (int tq = 0; tq < 4; tq++) {
        const uint32_t a = w[2 * tq],     b = w[2 * tq + 1];
        const uint32_t c = w[2 * tq + 8], d = w[2 * tq + 9];
        out[tq].x = __byte_perm(a, b, 0x5410);
        out[tq].y = __byte_perm(c, d, 0x5410);
        out[tq].z = __byte_perm(a, b, 0x7632);
        out[tq].w = __byte_perm(c, d, 0x7632);
    }
}

// ============================================================================
// tf32 tensor-core GEMM, 2-stage SMEM double buffering (unchanged, passing).
// ============================================================================
__global__ __launch_bounds__(256) void gemm_tf32(
    const float* __restrict__ A, const float* __restrict__ W,
    const float* __restrict__ bias1, const float* __restrict__ bias2,
    float* __restrict__ C, int K, int N, int xremap)
{
    __shared__ __align__(16) float As[2][128 * GS];
    __shared__ __align__(16) float Bs[2][128 * GS];

    const int m0 = blockIdx.x * 128;
    const int n0 = blockIdx.y * 128;
    const int tid = threadIdx.x;
    const int lane = tid & 31;
    const int warp = tid >> 5;
    const int gid = lane >> 2;
    const int tig = lane & 3;
    const int wm = (warp >> 2) * 64;
    const int wn = (warp & 3) * 32;

    const int srow = tid >> 1;
    const int skoff = (tid & 1) * 8;
    int arow = m0 + srow;
    if (xremap) {
        const int b = arow & (B_DIM - 1);
        const int t = arow >> 7;
        arow = b * T_DIM + t;
    }
    const float* ag = A + (long)arow * K + skoff;
    const float* bg = W + (long)(n0 + srow) * K + skoff;
    const int soff = srow * GS + skoff;

    float acc[4][4][4];
#pragma unroll
    for (int i = 0; i < 4; i++)
#pragma unroll
        for (int j = 0; j < 4; j++)
#pragma unroll
            for (int v = 0; v < 4; v++) acc[i][j][v] = 0.f;

    {
        float4 pa0 = *(const float4*)(ag);
        float4 pa1 = *(const float4*)(ag + 4);
        float4 pb0 = *(const float4*)(bg);
        float4 pb1 = *(const float4*)(bg + 4);
        st8tf_ilv(&As[0][soff], pa0, pa1);
        st8tf_ilv(&Bs[0][soff], pb0, pb1);
    }
    __syncthreads();

    const int nch = K >> 4;
    for (int c = 0; c < nch; c++) {
        const int s = c & 1;
        const bool more = (c + 1 < nch);
        float4 na0, na1, nb0, nb1;
        if (more) {
            const int ko = (c + 1) << 4;
            na0 = *(const float4*)(ag + ko);
            na1 = *(const float4*)(ag + ko + 4);
            nb0 = *(const float4*)(bg + ko);
            nb1 = *(const float4*)(bg + ko + 4);
        }
#pragma unroll
        for (int ks = 0; ks < 16; ks += 8) {
            const int kb = ks + 2 * tig;
            float2 alo[4], ahi[4], bf[4];
#pragma unroll
            for (int i = 0; i < 4; i++) {
                const float* ap = &As[s][(wm + i * 16 + gid) * GS + kb];
                alo[i] = *(const float2*)ap;
                ahi[i] = *(const float2*)(ap + 8 * GS);
            }
#pragma unroll
            for (int j = 0; j < 4; j++)
                bf[j] = *(const float2*)&Bs[s][(wn + j * 8 + gid) * GS + kb];
#pragma unroll
            for (int i = 0; i < 4; i++)
#pragma unroll
                for (int j = 0; j < 4; j++)
                    mma8(acc[i][j][0], acc[i][j][1], acc[i][j][2], acc[i][j][3],
                         __float_as_uint(alo[i].x), __float_as_uint(ahi[i].x),
                         __float_as_uint(alo[i].y), __float_as_uint(ahi[i].y),
                         __float_as_uint(bf[j].x), __float_as_uint(bf[j].y));
        }
        if (more) {
            st8tf_ilv(&As[s ^ 1][soff], na0, na1);
            st8tf_ilv(&Bs[s ^ 1][soff], nb0, nb1);
        }
        __syncthreads();
    }

#pragma unroll
    for (int j = 0; j < 4; j++) {
        const int n = n0 + wn + j * 8 + 2 * tig;
        float bz0 = bias1[n], bz1 = bias1[n + 1];
        if (bias2) { bz0 += bias2[n]; bz1 += bias2[n + 1]; }
#pragma unroll
        for (int i = 0; i < 4; i++) {
            const int m = m0 + wm + i * 16 + gid;
            float2 o1; o1.x = acc[i][j][0] + bz0; o1.y = acc[i][j][1] + bz1;
            float2 o2; o2.x = acc[i][j][2] + bz0; o2.y = acc[i][j][3] + bz1;
            *(float2*)(C + (long)m * N + n) = o1;
            *(float2*)(C + (long)(m + 8) * N + n) = o2;
        }
    }
}

// ============================================================================
// Grid-wide barrier (128 co-resident blocks, 1 block/SM).
// ============================================================================
__device__ __forceinline__ void grid_barrier()
{
    __threadfence();
    __syncthreads();
    if (threadIdx.x == 0) {
        const unsigned g = *(volatile unsigned int*)&g_bar_gen;
        const unsigned a = atomicAdd(&g_bar_cnt, 1u);
        if (a == NBLK - 1) {
            g_bar_cnt = 0;
            __threadfence();
            *(volatile unsigned int*)&g_bar_gen = g + 1u;
        } else {
            while (*(volatile unsigned int*)&g_bar_gen == g) __nanosleep(32);
        }
    }
    __syncthreads();
}

// ============================================================================
// Persistent LSTM layer, bf16-split tensor cores, W fragments in REGISTERS.
// 256 threads, warp w: gate g = w&3, k-half kh = w>>2.
// Phase 1: stage W slice into SMEM (chunk layout), each thread loads its 32
//          uint4 A-fragments into registers (loop-invariant across t).
// Phase 2: SMEM reused: hs [32][RSTR] + gx [2][64][GXS]. Per step only B
//          (h) fragments come from SMEM: 4 LDS.128 + 12 HMMA per k-chunk.
// ============================================================================
__global__ __launch_bounds__(256, 1) void lstm_layer_kernel(
    const float* __restrict__ h0, const float* __restrict__ c0,
    const float* __restrict__ Whh, const float* __restrict__ gates,
    float* __restrict__ seq, uint32_t* __restrict__ hpack,
    float* __restrict__ hT, float* __restrict__ cT)
{
    extern __shared__ uint32_t smem[];
    uint32_t* ws = smem;                       // phase 1: [64][RSTR]
    uint32_t* hs = smem;                       // phase 2: [32][RSTR]
    float*    gx = (float*)(smem + 32 * RSTR); // phase 2: [2][64][GXS]

    const int tid = threadIdx.x;
    const int lane = tid & 31;
    const int warp = tid >> 5;
    const int g = warp & 3;                    // gate
    const int kh = warp >> 2;                  // k-half
    const int fg = lane >> 2;                  // fragment group 0..7
    const int tq = lane & 3;

    const int mb = blockIdx.x & 31;
    const int bb = blockIdx.x >> 5;
    const int m0 = mb * 16;
    const int b0 = bb * 32;

    // ---- phase 1: stage W slice into SMEM chunk layout (one-time)
#pragma unroll
    for (int i = 0; i < 8; i++) {
        const int cell = tid + 256 * i;
        const int r = cell >> 5;
        const int ks = cell & 31;
        const int wg = r >> 4, mli = r & 15;
        const float* wrow = Whh + (long)(wg * HID + m0 + mli) * HID + ks * 16;
        float v[16];
#pragma unroll
        for (int q = 0; q < 4; q++) *(float4*)(v + 4 * q) = *(const float4*)(wrow + 4 * q);
        uint4 ck[4];
        make_chunks_f32(v, ck);
        uint32_t* dst = ws + r * RSTR + ks * 16;
#pragma unroll
        for (int q = 0; q < 4; q++) *(uint4*)(dst + 4 * q) = ck[q];
    }
    __syncthreads();

    // ---- preload this thread's A fragments into registers (32 x uint4)
    uint4 areg[16][2];
    {
        const uint32_t* wbase = ws + (g * 16) * RSTR;
        const int ks0 = kh * 16;
#pragma unroll
        for (int i = 0; i < 16; i++) {
            const int off = (ks0 + i) * 16 + tq * 4;
            areg[i][0] = *(const uint4*)(wbase + fg * RSTR + off);
            areg[i][1] = *(const uint4*)(wbase + (fg + 8) * RSTR + off);
        }
    }
    __syncthreads();   // all reads of ws done; smem may be reused as hs/gx

    // activation roles: thread = (ml 0..15, bh 0..15) -> 2 batches
    const int ml = tid & 15;
    const int bh = tid >> 4;
    const int lb0 = 2 * bh;
    const int m = m0 + ml;

    float creg[2];
#pragma unroll
    for (int j = 0; j < 2; j++)
        creg[j] = c0[(long)(b0 + lb0 + j) * HID + m];

    for (int t = 0; t < T_DIM; t++) {
        // prefetch this step's precomputed gate contributions
        const float* pre = gates + (long)t * B_DIM * G4;
        float pg[4][2];
#pragma unroll
        for (int gg = 0; gg < 4; gg++)
#pragma unroll
            for (int j = 0; j < 2; j++)
                pg[gg][j] = __ldcg(pre + (long)(b0 + lb0 + j) * G4 + (gg << 9) + m);

        // ---- stage h(t-1): cell = (sb, ks); 1024 cells / 256 threads
        if (t == 0) {
#pragma unroll
            for (int i = 0; i < 4; i++) {
                const int cell = tid + 256 * i;
                const int sb = cell >> 5;
                const int ks = cell & 31;
                const float* hrow = h0 + (long)(b0 + sb) * HID + ks * 16;
                float v[16];
#pragma unroll
                for (int q = 0; q < 4; q++) *(float4*)(v + 4 * q) = __ldcg((const float4*)(hrow + 4 * q));
                uint4 ck[4];
                make_chunks_f32(v, ck);
                uint32_t* dst = hs + sb * RSTR + ks * 16;
#pragma unroll
                for (int q = 0; q < 4; q++) *(uint4*)(dst + 4 * q) = ck[q];
            }
        } else {
#pragma unroll
            for (int i = 0; i < 4; i++) {
                const int cell = tid + 256 * i;
                const int sb = cell >> 5;
                const int ks = cell & 31;
                const uint32_t* hrow = hpack + (long)(b0 + sb) * HID + ks * 16;
                uint32_t u[16];
#pragma unroll
                for (int q = 0; q < 4; q++) *(uint4*)(u + 4 * q) = __ldcg((const uint4*)(hrow + 4 * q));
                uint4 ck[4];
                make_chunks_pk(u, ck);
                uint32_t* dst = hs + sb * RSTR + ks * 16;
#pragma unroll
                for (int q = 0; q < 4; q++) *(uint4*)(dst + 4 * q) = ck[q];
            }
        }
        __syncthreads();   // hs ready

        // ---- mma: warp computes gate g, k-half kh, all 32 batches
        float acc[4][4];
#pragma unroll
        for (int j = 0; j < 4; j++)
#pragma unroll
            for (int v = 0; v < 4; v++) acc[j][v] = 0.f;

        const int ks0 = kh * 16;
#pragma unroll
        for (int i = 0; i < 16; i++) {
            const int off = (ks0 + i) * 16 + tq * 4;
            const uint4 A0 = areg[i][0];
            const uint4 A1 = areg[i][1];
#pragma unroll
            for (int j = 0; j < 4; j++) {
                const uint4 Bv = *(const uint4*)(hs + (8 * j + fg) * RSTR + off);
                mma16bf(acc[j][0], acc[j][1], acc[j][2], acc[j][3],
                        A0.x, A1.x, A0.y, A1.y, Bv.x, Bv.y);   // hi*hi
                mma16bf(acc[j][0], acc[j][1], acc[j][2], acc[j][3],
                        A0.x, A1.x, A0.y, A1.y, Bv.z, Bv.w);   // hi*lo
                mma16bf(acc[j][0], acc[j][1], acc[j][2], acc[j][3],
                        A0.z, A1.z, A0.w, A1.w, Bv.x, Bv.y);   // lo*hi
            }
        }

        // ---- write partial gates to this k-half's exchange plane
        float* gxp = gx + kh * (64 * GXS);
#pragma unroll
        for (int j = 0; j < 4; j++) {
            float2 lo2; lo2.x = acc[j][0]; lo2.y = acc[j][1];
            float2 hi2; hi2.x = acc[j][2]; hi2.y = acc[j][3];
            *(float2*)&gxp[(g * 16 + fg) * GXS + 8 * j + 2 * tq] = lo2;
            *(float2*)&gxp[(g * 16 + fg + 8) * GXS + 8 * j + 2 * tq] = hi2;
        }
        __syncthreads();

        // ---- activations: sum k-halves, update state, write h
        float gate[4][2];
#pragma unroll
        for (int gg = 0; gg < 4; gg++) {
            const float2 p0 = *(const float2*)&gx[(gg * 16 + ml) * GXS + lb0];
            const float2 p1 = *(const float2*)&gx[64 * GXS + (gg * 16 + ml) * GXS + lb0];
            gate[gg][0] = p0.x + p1.x;
            gate[gg][1] = p0.y + p1.y;
        }

        float* hrow = seq + (long)t * STATE;
#pragma unroll
        for (int j = 0; j < 2; j++) {
            const int b = b0 + lb0 + j;
            const float gi = gate[0][j] + pg[0][j];
            const float gf = gate[1][j] + pg[1][j];
            const float gg = gate[2][j] + pg[2][j];
            const float go = gate[3][j] + pg[3][j];
            const float i_ = 1.f / (1.f + expf(-gi));
            const float f_ = 1.f / (1.f + expf(-gf));
            const float g_ = tanhf(gg);
            const float o_ = 1.f / (1.f + expf(-go));
            const float c = f_ * creg[j] + i_ * g_;
            creg[j] = c;
            const float h = o_ * tanhf(c);
            hpack[(long)b * HID + m] = hpk(h);
            hrow[(long)b * HID + m] = h;
            if (t == T_DIM - 1) {
                hT[(long)b * HID + m] = h;
                cT[(long)b * HID + m] = c;
            }
        }

        grid_barrier();    // publish h(t)/hpack(t); also guards hs reuse
    }
}

// ============================================================================
// LayerNorm + (t,b)->(b,t) transpose (unchanged).
// ============================================================================
__global__ __launch_bounds__(256) void ln_out_kernel(
    const float* __restrict__ X, const float* __restrict__ gamma,
    const float* __restrict__ beta, float* __restrict__ out)
{
    const int row = blockIdx.x;
    const float* x = X + (long)row * OUT_DIM;
    const int tid = threadIdx.x;

    const float v0 = x[tid];
    const float v1 = x[tid + 256];
    const float v2 = x[tid + 512];

    __shared__ float red[8];
    __shared__ float s_mu, s_rs;

    float s = v0 + v1 + v2;
#pragma unroll
    for (int o = 16; o > 0; o >>= 1) s += __shfl_down_sync(0xffffffffu, s, o);
    if ((tid & 31) == 0) red[tid >> 5] = s;
    __syncthreads();
    if (tid == 0) {
        float tot = 0.f;
#pragma unroll
        for (int i = 0; i < 8; i++) tot += red[i];
        s_mu = tot * (1.f / OUT_DIM);
    }
    __syncthreads();
    const float mu = s_mu;
    const float d0 = v0 - mu, d1 = v1 - mu, d2 = v2 - mu;

    float q = d0 * d0 + d1 * d1 + d2 * d2;
#pragma unroll
    for (int o = 16; o > 0; o >>= 1) q += __shfl_down_sync(0xffffffffu, q, o);
    if ((tid & 31) == 0) red[tid >> 5] = q;
    __syncthreads();
    if (tid == 0) {
        float tot = 0.f;
#pragma unroll
        for (int i = 0; i < 8; i++) tot += red[i];
        s_rs = rsqrtf(tot * (1.f / OUT_DIM) + 1e-5f);
    }
    __syncthreads();
    const float rs = s_rs;

    const int b = row & (B_DIM - 1);
    const int t = row >> 7;
    float* o = out + (long)(b * T_DIM + t) * OUT_DIM;
    o[tid]       = d0 * rs * gamma[tid]       + beta[tid];
    o[tid + 256] = d1 * rs * gamma[tid + 256] + beta[tid + 256];
    o[tid + 512] = d2 * rs * gamma[tid + 512] + beta[tid + 512];
}

// ============================================================================
extern "C" void kernel_launch(void* const* d_in, const int* in_sizes, int n_in,
                              void* d_out, int out_size)
{
    const float* x     = (const float*)d_in[0];
    const float* h0    = (const float*)d_in[1];
    const float* c0    = (const float*)d_in[2];
    const float* W_in  = (const float*)d_in[3];
    const float* b_in  = (const float*)d_in[4];
    const float* W_ih  = (const float*)d_in[5];
    const float* W_hh  = (const float*)d_in[6];
    const float* b_ih  = (const float*)d_in[7];
    const float* b_hh  = (const float*)d_in[8];
    const float* W_out = (const float*)d_in[9];
    const float* b_out = (const float*)d_in[10];
    const float* ln_g  = (const float*)d_in[11];
    const float* ln_b  = (const float*)d_in[12];
    float* out = (float*)d_out;

    float *seqA, *seqB, *gates, *outp;
    uint32_t* hpack;
    cudaGetSymbolAddress((void**)&seqA, g_seqA);
    cudaGetSymbolAddress((void**)&seqB, g_seqB);
    cudaGetSymbolAddress((void**)&gates, g_gates);
    cudaGetSymbolAddress((void**)&outp, g_outp);
    cudaGetSymbolAddress((void**)&hpack, g_hpack);

    // phase-1 (W staging) footprint dominates: 64*RSTR u32 = 135168 B
    int ws_bytes = 64 * RSTR * 4;
    int ph2_bytes = 32 * RSTR * 4 + 2 * 64 * GXS * 4;
    const int lstm_smem = ws_bytes > ph2_bytes ? ws_bytes : ph2_bytes;
    cudaFuncSetAttribute(lstm_layer_kernel,
                         cudaFuncAttributeMaxDynamicSharedMemorySize, lstm_smem);

    const long OUT_ELEMS = (long)B_DIM * T_DIM * OUT_DIM;

    // 1) input projection with (b,t)->(t,b) transpose (tf32 TC)
    gemm_tf32<<<dim3(ROWS / 128, HID / 128), 256>>>(x, W_in, b_in, nullptr, seqA,
                                                    INP_DIM, HID, 1);

    for (int l = 0; l < NL; l++) {
        const float* in = (l & 1) ? seqB : seqA;
        float* outSeq   = (l & 1) ? seqA : seqB;

        // 2a) parallel: gates = in @ W_ih[l]^T + b_ih[l] + b_hh[l] (tf32 TC)
        gemm_tf32<<<dim3(ROWS / 128, G4 / 128), 256>>>(
            in, W_ih + (long)l * G4 * HID, b_ih + l * G4, b_hh + l * G4,
            gates, HID, G4, 0);

        // 2b) serial recurrence: persistent, bf16-split TC, W in registers
        lstm_layer_kernel<<<NBLK, 256, lstm_smem>>>(
            h0 + (long)l * STATE, c0 + (long)l * STATE,
            W_hh + (long)l * G4 * HID, gates, outSeq, hpack,
            out + OUT_ELEMS + (long)l * STATE,
            out + OUT_ELEMS + (long)NL * STATE + (long)l * STATE);
    }

    // 3) output projection (tf32 TC)
    gemm_tf32<<<dim3(ROWS / 128, OUT_DIM / 128), 256>>>(seqA, W_out, b_out, nullptr,
                                                        outp, HID, OUT_DIM, 0);

    // 4) layernorm + transpose into d_out
    ln_out_kernel<<<ROWS, 256>>>(outp, ln_g, ln_b, out);
}

// round 11
// speedup vs baseline: 2.3098x; 1.0055x over previous
#include <cuda_runtime.h>
#include <cuda_bf16.h>
#include <math.h>
#include <stdint.h>

#define T_DIM 256
#define B_DIM 128
#define INP_DIM 768
#define HID 512
#define OUT_DIM 768
#define NL 4
#define G4 (4 * HID)            // 2048
#define ROWS (T_DIM * B_DIM)    // 32768
#define STATE (B_DIM * HID)     // 65536

#define NBLK 128                // persistent recurrence grid (<= SM count)
#define NGRP 4                  // independent barrier groups (one per bb)
#define GRP_BLKS 32             // blocks per group
#define GS 24                   // ff-gemm SMEM row stride (floats)

// recurrence chunked SMEM row stride (u32). 528*4 = 2112 B, 2112 mod 128 = 64
// -> every LDS.128 phase (8 lanes) conflict-free.
#define RSTR 528
#define GXS 36                  // gate-exchange stride (floats)

// ---------------- scratch (static device globals: no allocation) ----------------
__device__ float g_seqA[ROWS * HID];
__device__ float g_seqB[ROWS * HID];
__device__ float g_gates[ROWS * G4];
__device__ float g_outp[ROWS * OUT_DIM];
__device__ uint32_t g_hpack[STATE];      // h packed as (bf16 hi | bf16 lo << 16)

// per-group barrier state, 128B apart (32 u32 stride)
__device__ unsigned int g_bar_cnt4[NGRP * 32];
__device__ unsigned int g_bar_gen4[NGRP * 32];

// ---------------- tf32 helpers (FF GEMM) ----------------
__device__ __forceinline__ uint32_t f2tf(float f) {
    uint32_t u;
    asm("cvt.rna.tf32.f32 %0, %1;" : "=r"(u) : "f"(f));
    return u;
}
__device__ __forceinline__ void st8tf_ilv(float* p, float4 v0, float4 v1) {
    float4 t0, t1;
    t0.x = __uint_as_float(f2tf(v0.x));
    t0.y = __uint_as_float(f2tf(v1.x));
    t0.z = __uint_as_float(f2tf(v0.y));
    t0.w = __uint_as_float(f2tf(v1.y));
    t1.x = __uint_as_float(f2tf(v0.z));
    t1.y = __uint_as_float(f2tf(v1.z));
    t1.z = __uint_as_float(f2tf(v0.w));
    t1.w = __uint_as_float(f2tf(v1.w));
    *(float4*)p = t0;
    *(float4*)(p + 4) = t1;
}
__device__ __forceinline__ void mma8(float& c0, float& c1, float& c2, float& c3,
                                     uint32_t a0, uint32_t a1, uint32_t a2, uint32_t a3,
                                     uint32_t b0, uint32_t b1) {
    asm volatile("mma.sync.aligned.m16n8k8.row.col.f32.tf32.tf32.f32 "
                 "{%0,%1,%2,%3}, {%4,%5,%6,%7}, {%8,%9}, {%0,%1,%2,%3};"
                 : "+f"(c0), "+f"(c1), "+f"(c2), "+f"(c3)
                 : "r"(a0), "r"(a1), "r"(a2), "r"(a3), "r"(b0), "r"(b1));
}

// ---------------- bf16 helpers (recurrence) ----------------
__device__ __forceinline__ void mma16bf(float& c0, float& c1, float& c2, float& c3,
                                        uint32_t a0, uint32_t a1, uint32_t a2, uint32_t a3,
                                        uint32_t b0, uint32_t b1) {
    asm volatile("mma.sync.aligned.m16n8k16.row.col.f32.bf16.bf16.f32 "
                 "{%0,%1,%2,%3}, {%4,%5,%6,%7}, {%8,%9}, {%0,%1,%2,%3};"
                 : "+f"(c0), "+f"(c1), "+f"(c2), "+f"(c3)
                 : "r"(a0), "r"(a1), "r"(a2), "r"(a3), "r"(b0), "r"(b1));
}
__device__ __forceinline__ uint32_t split_pair(float a, float b, uint32_t& lo) {
    __nv_bfloat16 ah = __float2bfloat16_rn(a);
    __nv_bfloat16 bh = __float2bfloat16_rn(b);
    __nv_bfloat16 al = __float2bfloat16_rn(a - __bfloat162float(ah));
    __nv_bfloat16 bl = __float2bfloat16_rn(b - __bfloat162float(bh));
    lo = (uint32_t)__bfloat16_as_ushort(al) | ((uint32_t)__bfloat16_as_ushort(bl) << 16);
    return (uint32_t)__bfloat16_as_ushort(ah) | ((uint32_t)__bfloat16_as_ushort(bh) << 16);
}
__device__ __forceinline__ uint32_t hpk(float h) {
    __nv_bfloat16 hi = __float2bfloat16_rn(h);
    __nv_bfloat16 lo = __float2bfloat16_rn(h - __bfloat162float(hi));
    return (uint32_t)__bfloat16_as_ushort(hi) | ((uint32_t)__bfloat16_as_ushort(lo) << 16);
}

// Build 4 16B chunks {hi(tq),hi(tq+4),lo(tq),lo(tq+4)} from 16 fp32 values.
__device__ __forceinline__ void make_chunks_f32(const float* v, uint4* out) {
    uint32_t hi[8], lo[8];
#pragma unroll
    for (int p = 0; p < 8; p++) hi[p] = split_pair(v[2 * p], v[2 * p + 1], lo[p]);
#pragma unroll
    for (int tq = 0; tq < 4; tq++) {
        out[tq].x = hi[tq];
        out[tq].y = hi[tq + 4];
        out[tq].z = lo[tq];
        out[tq].w = lo[tq + 4];
    }
}
// Same from 16 hpack-packed u32 values (hi|lo<<16).
__device__ __forceinline__ void make_chunks_pk(const uint32_t* w, uint4* out) {
#pragma unroll
    for (int tq = 0; tq < 4; tq++) {
        const uint32_t a = w[2 * tq],     b = w[2 * tq + 1];
        const uint32_t c = w[2 * tq + 8], d = w[2 * tq + 9];
        out[tq].x = __byte_perm(a, b, 0x5410);
        out[tq].y = __byte_perm(c, d, 0x5410);
        out[tq].z = __byte_perm(a, b, 0x7632);
        out[tq].w = __byte_perm(c, d, 0x7632);
    }
}

// ============================================================================
// tf32 tensor-core GEMM, 2-stage SMEM double buffering (unchanged, passing).
// ============================================================================
__global__ __launch_bounds__(256) void gemm_tf32(
    const float* __restrict__ A, const float* __restrict__ W,
    const float* __restrict__ bias1, const float* __restrict__ bias2,
    float* __restrict__ C, int K, int N, int xremap)
{
    __shared__ __align__(16) float As[2][128 * GS];
    __shared__ __align__(16) float Bs[2][128 * GS];

    const int m0 = blockIdx.x * 128;
    const int n0 = blockIdx.y * 128;
    const int tid = threadIdx.x;
    const int lane = tid & 31;
    const int warp = tid >> 5;
    const int gid = lane >> 2;
    const int tig = lane & 3;
    const int wm = (warp >> 2) * 64;
    const int wn = (warp & 3) * 32;

    const int srow = tid >> 1;
    const int skoff = (tid & 1) * 8;
    int arow = m0 + srow;
    if (xremap) {
        const int b = arow & (B_DIM - 1);
        const int t = arow >> 7;
        arow = b * T_DIM + t;
    }
    const float* ag = A + (long)arow * K + skoff;
    const float* bg = W + (long)(n0 + srow) * K + skoff;
    const int soff = srow * GS + skoff;

    float acc[4][4][4];
#pragma unroll
    for (int i = 0; i < 4; i++)
#pragma unroll
        for (int j = 0; j < 4; j++)
#pragma unroll
            for (int v = 0; v < 4; v++) acc[i][j][v] = 0.f;

    {
        float4 pa0 = *(const float4*)(ag);
        float4 pa1 = *(const float4*)(ag + 4);
        float4 pb0 = *(const float4*)(bg);
        float4 pb1 = *(const float4*)(bg + 4);
        st8tf_ilv(&As[0][soff], pa0, pa1);
        st8tf_ilv(&Bs[0][soff], pb0, pb1);
    }
    __syncthreads();

    const int nch = K >> 4;
    for (int c = 0; c < nch; c++) {
        const int s = c & 1;
        const bool more = (c + 1 < nch);
        float4 na0, na1, nb0, nb1;
        if (more) {
            const int ko = (c + 1) << 4;
            na0 = *(const float4*)(ag + ko);
            na1 = *(const float4*)(ag + ko + 4);
            nb0 = *(const float4*)(bg + ko);
            nb1 = *(const float4*)(bg + ko + 4);
        }
#pragma unroll
        for (int ks = 0; ks < 16; ks += 8) {
            const int kb = ks + 2 * tig;
            float2 alo[4], ahi[4], bf[4];
#pragma unroll
            for (int i = 0; i < 4; i++) {
                const float* ap = &As[s][(wm + i * 16 + gid) * GS + kb];
                alo[i] = *(const float2*)ap;
                ahi[i] = *(const float2*)(ap + 8 * GS);
            }
#pragma unroll
            for (int j = 0; j < 4; j++)
                bf[j] = *(const float2*)&Bs[s][(wn + j * 8 + gid) * GS + kb];
#pragma unroll
            for (int i = 0; i < 4; i++)
#pragma unroll
                for (int j = 0; j < 4; j++)
                    mma8(acc[i][j][0], acc[i][j][1], acc[i][j][2], acc[i][j][3],
                         __float_as_uint(alo[i].x), __float_as_uint(ahi[i].x),
                         __float_as_uint(alo[i].y), __float_as_uint(ahi[i].y),
                         __float_as_uint(bf[j].x), __float_as_uint(bf[j].y));
        }
        if (more) {
            st8tf_ilv(&As[s ^ 1][soff], na0, na1);
            st8tf_ilv(&Bs[s ^ 1][soff], nb0, nb1);
        }
        __syncthreads();
    }

#pragma unroll
    for (int j = 0; j < 4; j++) {
        const int n = n0 + wn + j * 8 + 2 * tig;
        float bz0 = bias1[n], bz1 = bias1[n + 1];
        if (bias2) { bz0 += bias2[n]; bz1 += bias2[n + 1]; }
#pragma unroll
        for (int i = 0; i < 4; i++) {
            const int m = m0 + wm + i * 16 + gid;
            float2 o1; o1.x = acc[i][j][0] + bz0; o1.y = acc[i][j][1] + bz1;
            float2 o2; o2.x = acc[i][j][2] + bz0; o2.y = acc[i][j][3] + bz1;
            *(float2*)(C + (long)m * N + n) = o1;
            *(float2*)(C + (long)(m + 8) * N + n) = o2;
        }
    }
}

// ============================================================================
// Group barrier: 32 co-resident blocks sharing one bb (batch range).
// Legal because all cross-block dataflow inside a layer (h/hpack) is confined
// to blocks with the same bb. Generation monotone across replays; counter
// resets inside each barrier. Tight L2 spin (no nanosleep) for fast wakeup.
// ============================================================================
__device__ __forceinline__ void group_barrier(int grp)
{
    __threadfence();
    __syncthreads();
    if (threadIdx.x == 0) {
        volatile unsigned int* genp = &g_bar_gen4[grp * 32];
        const unsigned g = *genp;
        const unsigned a = atomicAdd(&g_bar_cnt4[grp * 32], 1u);
        if (a == GRP_BLKS - 1) {
            g_bar_cnt4[grp * 32] = 0;
            __threadfence();
            *genp = g + 1u;
        } else {
            while (*genp == g) { }
        }
    }
    __syncthreads();
}

// ============================================================================
// Persistent LSTM layer, bf16-split tensor cores, W fragments in registers,
// per-bb-group barriers. (mma/staging identical to R10, passing.)
// ============================================================================
__global__ __launch_bounds__(256, 1) void lstm_layer_kernel(
    const float* __restrict__ h0, const float* __restrict__ c0,
    const float* __restrict__ Whh, const float* __restrict__ gates,
    float* __restrict__ seq, uint32_t* __restrict__ hpack,
    float* __restrict__ hT, float* __restrict__ cT)
{
    extern __shared__ uint32_t smem[];
    uint32_t* ws = smem;                       // phase 1: [64][RSTR]
    uint32_t* hs = smem;                       // phase 2: [32][RSTR]
    float*    gx = (float*)(smem + 32 * RSTR); // phase 2: [2][64][GXS]

    const int tid = threadIdx.x;
    const int lane = tid & 31;
    const int warp = tid >> 5;
    const int g = warp & 3;                    // gate
    const int kh = warp >> 2;                  // k-half
    const int fg = lane >> 2;                  // fragment group 0..7
    const int tq = lane & 3;

    const int mb = blockIdx.x & 31;
    const int bb = blockIdx.x >> 5;            // barrier group
    const int m0 = mb * 16;
    const int b0 = bb * 32;

    // ---- phase 1: stage W slice into SMEM chunk layout (one-time)
#pragma unroll
    for (int i = 0; i < 8; i++) {
        const int cell = tid + 256 * i;
        const int r = cell >> 5;
        const int ks = cell & 31;
        const int wg = r >> 4, mli = r & 15;
        const float* wrow = Whh + (long)(wg * HID + m0 + mli) * HID + ks * 16;
        float v[16];
#pragma unroll
        for (int q = 0; q < 4; q++) *(float4*)(v + 4 * q) = *(const float4*)(wrow + 4 * q);
        uint4 ck[4];
        make_chunks_f32(v, ck);
        uint32_t* dst = ws + r * RSTR + ks * 16;
#pragma unroll
        for (int q = 0; q < 4; q++) *(uint4*)(dst + 4 * q) = ck[q];
    }
    __syncthreads();

    // ---- preload A fragments into registers (loop-invariant across t)
    uint4 areg[16][2];
    {
        const uint32_t* wbase = ws + (g * 16) * RSTR;
        const int ks0 = kh * 16;
#pragma unroll
        for (int i = 0; i < 16; i++) {
            const int off = (ks0 + i) * 16 + tq * 4;
            areg[i][0] = *(const uint4*)(wbase + fg * RSTR + off);
            areg[i][1] = *(const uint4*)(wbase + (fg + 8) * RSTR + off);
        }
    }
    __syncthreads();   // ws reads done; smem reused as hs/gx

    // activation roles: thread = (ml 0..15, bh 0..15) -> 2 batches
    const int ml = tid & 15;
    const int bh = tid >> 4;
    const int lb0 = 2 * bh;
    const int m = m0 + ml;

    float creg[2];
#pragma unroll
    for (int j = 0; j < 2; j++)
        creg[j] = c0[(long)(b0 + lb0 + j) * HID + m];

    for (int t = 0; t < T_DIM; t++) {
        const float* pre = gates + (long)t * B_DIM * G4;
        float pg[4][2];
#pragma unroll
        for (int gg = 0; gg < 4; gg++)
#pragma unroll
            for (int j = 0; j < 2; j++)
                pg[gg][j] = __ldcg(pre + (long)(b0 + lb0 + j) * G4 + (gg << 9) + m);

        // ---- stage h(t-1)
        if (t == 0) {
#pragma unroll
            for (int i = 0; i < 4; i++) {
                const int cell = tid + 256 * i;
                const int sb = cell >> 5;
                const int ks = cell & 31;
                const float* hrow = h0 + (long)(b0 + sb) * HID + ks * 16;
                float v[16];
#pragma unroll
                for (int q = 0; q < 4; q++) *(float4*)(v + 4 * q) = __ldcg((const float4*)(hrow + 4 * q));
                uint4 ck[4];
                make_chunks_f32(v, ck);
                uint32_t* dst = hs + sb * RSTR + ks * 16;
#pragma unroll
                for (int q = 0; q < 4; q++) *(uint4*)(dst + 4 * q) = ck[q];
            }
        } else {
#pragma unroll
            for (int i = 0; i < 4; i++) {
                const int cell = tid + 256 * i;
                const int sb = cell >> 5;
                const int ks = cell & 31;
                const uint32_t* hrow = hpack + (long)(b0 + sb) * HID + ks * 16;
                uint32_t u[16];
#pragma unroll
                for (int q = 0; q < 4; q++) *(uint4*)(u + 4 * q) = __ldcg((const uint4*)(hrow + 4 * q));
                uint4 ck[4];
                make_chunks_pk(u, ck);
                uint32_t* dst = hs + sb * RSTR + ks * 16;
#pragma unroll
                for (int q = 0; q < 4; q++) *(uint4*)(dst + 4 * q) = ck[q];
            }
        }
        __syncthreads();   // hs ready

        // ---- mma: warp computes gate g, k-half kh, all 32 batches
        float acc[4][4];
#pragma unroll
        for (int j = 0; j < 4; j++)
#pragma unroll
            for (int v = 0; v < 4; v++) acc[j][v] = 0.f;

        const int ks0 = kh * 16;
#pragma unroll
        for (int i = 0; i < 16; i++) {
            const int off = (ks0 + i) * 16 + tq * 4;
            const uint4 A0 = areg[i][0];
            const uint4 A1 = areg[i][1];
#pragma unroll
            for (int j = 0; j < 4; j++) {
                const uint4 Bv = *(const uint4*)(hs + (8 * j + fg) * RSTR + off);
                mma16bf(acc[j][0], acc[j][1], acc[j][2], acc[j][3],
                        A0.x, A1.x, A0.y, A1.y, Bv.x, Bv.y);   // hi*hi
                mma16bf(acc[j][0], acc[j][1], acc[j][2], acc[j][3],
                        A0.x, A1.x, A0.y, A1.y, Bv.z, Bv.w);   // hi*lo
                mma16bf(acc[j][0], acc[j][1], acc[j][2], acc[j][3],
                        A0.z, A1.z, A0.w, A1.w, Bv.x, Bv.y);   // lo*hi
            }
        }

        // ---- write partial gates to this k-half's exchange plane
        float* gxp = gx + kh * (64 * GXS);
#pragma unroll
        for (int j = 0; j < 4; j++) {
            float2 lo2; lo2.x = acc[j][0]; lo2.y = acc[j][1];
            float2 hi2; hi2.x = acc[j][2]; hi2.y = acc[j][3];
            *(float2*)&gxp[(g * 16 + fg) * GXS + 8 * j + 2 * tq] = lo2;
            *(float2*)&gxp[(g * 16 + fg + 8) * GXS + 8 * j + 2 * tq] = hi2;
        }
        __syncthreads();

        // ---- activations: sum k-halves, update state, write h
        float gate[4][2];
#pragma unroll
        for (int gg = 0; gg < 4; gg++) {
            const float2 p0 = *(const float2*)&gx[(gg * 16 + ml) * GXS + lb0];
            const float2 p1 = *(const float2*)&gx[64 * GXS + (gg * 16 + ml) * GXS + lb0];
            gate[gg][0] = p0.x + p1.x;
            gate[gg][1] = p0.y + p1.y;
        }

        float* hrow = seq + (long)t * STATE;
#pragma unroll
        for (int j = 0; j < 2; j++) {
            const int b = b0 + lb0 + j;
            const float gi = gate[0][j] + pg[0][j];
            const float gf = gate[1][j] + pg[1][j];
            const float gg = gate[2][j] + pg[2][j];
            const float go = gate[3][j] + pg[3][j];
            const float i_ = 1.f / (1.f + expf(-gi));
            const float f_ = 1.f / (1.f + expf(-gf));
            const float g_ = tanhf(gg);
            const float o_ = 1.f / (1.f + expf(-go));
            const float c = f_ * creg[j] + i_ * g_;
            creg[j] = c;
            const float h = o_ * tanhf(c);
            hpack[(long)b * HID + m] = hpk(h);
            hrow[(long)b * HID + m] = h;
            if (t == T_DIM - 1) {
                hT[(long)b * HID + m] = h;
                cT[(long)b * HID + m] = c;
            }
        }

        group_barrier(bb);   // only the 32 blocks sharing this batch range
    }
}

// ============================================================================
// LayerNorm + (t,b)->(b,t) transpose (unchanged).
// ============================================================================
__global__ __launch_bounds__(256) void ln_out_kernel(
    const float* __restrict__ X, const float* __restrict__ gamma,
    const float* __restrict__ beta, float* __restrict__ out)
{
    const int row = blockIdx.x;
    const float* x = X + (long)row * OUT_DIM;
    const int tid = threadIdx.x;

    const float v0 = x[tid];
    const float v1 = x[tid + 256];
    const float v2 = x[tid + 512];

    __shared__ float red[8];
    __shared__ float s_mu, s_rs;

    float s = v0 + v1 + v2;
#pragma unroll
    for (int o = 16; o > 0; o >>= 1) s += __shfl_down_sync(0xffffffffu, s, o);
    if ((tid & 31) == 0) red[tid >> 5] = s;
    __syncthreads();
    if (tid == 0) {
        float tot = 0.f;
#pragma unroll
        for (int i = 0; i < 8; i++) tot += red[i];
        s_mu = tot * (1.f / OUT_DIM);
    }
    __syncthreads();
    const float mu = s_mu;
    const float d0 = v0 - mu, d1 = v1 - mu, d2 = v2 - mu;

    float q = d0 * d0 + d1 * d1 + d2 * d2;
#pragma unroll
    for (int o = 16; o > 0; o >>= 1) q += __shfl_down_sync(0xffffffffu, q, o);
    if ((tid & 31) == 0) red[tid >> 5] = q;
    __syncthreads();
    if (tid == 0) {
        float tot = 0.f;
#pragma unroll
        for (int i = 0; i < 8; i++) tot += red[i];
        s_rs = rsqrtf(tot * (1.f / OUT_DIM) + 1e-5f);
    }
    __syncthreads();
    const float rs = s_rs;

    const int b = row & (B_DIM - 1);
    const int t = row >> 7;
    float* o = out + (long)(b * T_DIM + t) * OUT_DIM;
    o[tid]       = d0 * rs * gamma[tid]       + beta[tid];
    o[tid + 256] = d1 * rs * gamma[tid + 256] + beta[tid + 256];
    o[tid + 512] = d2 * rs * gamma[tid + 512] + beta[tid + 512];
}

// ============================================================================
extern "C" void kernel_launch(void* const* d_in, const int* in_sizes, int n_in,
                              void* d_out, int out_size)
{
    const float* x     = (const float*)d_in[0];
    const float* h0    = (const float*)d_in[1];
    const float* c0    = (const float*)d_in[2];
    const float* W_in  = (const float*)d_in[3];
    const float* b_in  = (const float*)d_in[4];
    const float* W_ih  = (const float*)d_in[5];
    const float* W_hh  = (const float*)d_in[6];
    const float* b_ih  = (const float*)d_in[7];
    const float* b_hh  = (const float*)d_in[8];
    const float* W_out = (const float*)d_in[9];
    const float* b_out = (const float*)d_in[10];
    const float* ln_g  = (const float*)d_in[11];
    const float* ln_b  = (const float*)d_in[12];
    float* out = (float*)d_out;

    float *seqA, *seqB, *gates, *outp;
    uint32_t* hpack;
    cudaGetSymbolAddress((void**)&seqA, g_seqA);
    cudaGetSymbolAddress((void**)&seqB, g_seqB);
    cudaGetSymbolAddress((void**)&gates, g_gates);
    cudaGetSymbolAddress((void**)&outp, g_outp);
    cudaGetSymbolAddress((void**)&hpack, g_hpack);

    int ws_bytes = 64 * RSTR * 4;
    int ph2_bytes = 32 * RSTR * 4 + 2 * 64 * GXS * 4;
    const int lstm_smem = ws_bytes > ph2_bytes ? ws_bytes : ph2_bytes;
    cudaFuncSetAttribute(lstm_layer_kernel,
                         cudaFuncAttributeMaxDynamicSharedMemorySize, lstm_smem);

    const long OUT_ELEMS = (long)B_DIM * T_DIM * OUT_DIM;

    // 1) input projection with (b,t)->(t,b) transpose (tf32 TC)
    gemm_tf32<<<dim3(ROWS / 128, HID / 128), 256>>>(x, W_in, b_in, nullptr, seqA,
                                                    INP_DIM, HID, 1);

    for (int l = 0; l < NL; l++) {
        const float* in = (l & 1) ? seqB : seqA;
        float* outSeq   = (l & 1) ? seqA : seqB;

        // 2a) parallel: gates = in @ W_ih[l]^T + b_ih[l] + b_hh[l] (tf32 TC)
        gemm_tf32<<<dim3(ROWS / 128, G4 / 128), 256>>>(
            in, W_ih + (long)l * G4 * HID, b_ih + l * G4, b_hh + l * G4,
            gates, HID, G4, 0);

        // 2b) serial recurrence: persistent, bf16-split TC, group barriers
        lstm_layer_kernel<<<NBLK, 256, lstm_smem>>>(
            h0 + (long)l * STATE, c0 + (long)l * STATE,
            W_hh + (long)l * G4 * HID, gates, outSeq, hpack,
            out + OUT_ELEMS + (long)l * STATE,
            out + OUT_ELEMS + (long)NL * STATE + (long)l * STATE);
    }

    // 3) output projection (tf32 TC)
    gemm_tf32<<<dim3(ROWS / 128, OUT_DIM / 128), 256>>>(seqA, W_out, b_out, nullptr,
                                                        outp, HID, OUT_DIM, 0);

    // 4) layernorm + transpose into d_out
    ln_out_kernel<<<ROWS, 256>>>(outp, ln_g, ln_b, out);
}

// round 12
// speedup vs baseline: 2.3372x; 1.0119x over previous
#include <cuda_runtime.h>
#include <cuda_bf16.h>
#include <math.h>
#include <stdint.h>

#define T_DIM 256
#define B_DIM 128
#define INP_DIM 768
#define HID 512
#define OUT_DIM 768
#define NL 4
#define G4 (4 * HID)            // 2048
#define ROWS (T_DIM * B_DIM)    // 32768
#define STATE (B_DIM * HID)     // 65536

#define NBLK 128                // persistent recurrence grid (<= SM count)
#define NGRP 4                  // independent barrier groups (one per bb)
#define GRP_BLKS 32             // blocks per group
#define GS 24                   // ff-gemm SMEM row stride (floats)

// recurrence chunked SMEM row stride (u32). 528*4 = 2112 B, 2112 mod 128 = 64
// -> every LDS.128 phase (8 lanes) conflict-free.
#define RSTR 528
#define GXS 36                  // gate-exchange stride (floats)

// ---------------- scratch (static device globals: no allocation) ----------------
__device__ float g_seqA[ROWS * HID];
__device__ float g_seqB[ROWS * HID];
__device__ float g_gates[ROWS * G4];
__device__ float g_outp[ROWS * OUT_DIM];
__device__ uint32_t g_hpack[STATE];      // h packed as (bf16 hi | bf16 lo << 16)

// per-group barrier state, 128B apart (32 u32 stride)
__device__ unsigned int g_bar_cnt4[NGRP * 32];
__device__ unsigned int g_bar_gen4[NGRP * 32];

// ---------------- tf32 helpers (FF GEMM) ----------------
__device__ __forceinline__ uint32_t f2tf(float f) {
    uint32_t u;
    asm("cvt.rna.tf32.f32 %0, %1;" : "=r"(u) : "f"(f));
    return u;
}
__device__ __forceinline__ void st8tf_ilv(float* p, float4 v0, float4 v1) {
    float4 t0, t1;
    t0.x = __uint_as_float(f2tf(v0.x));
    t0.y = __uint_as_float(f2tf(v1.x));
    t0.z = __uint_as_float(f2tf(v0.y));
    t0.w = __uint_as_float(f2tf(v1.y));
    t1.x = __uint_as_float(f2tf(v0.z));
    t1.y = __uint_as_float(f2tf(v1.z));
    t1.z = __uint_as_float(f2tf(v0.w));
    t1.w = __uint_as_float(f2tf(v1.w));
    *(float4*)p = t0;
    *(float4*)(p + 4) = t1;
}
__device__ __forceinline__ void mma8(float& c0, float& c1, float& c2, float& c3,
                                     uint32_t a0, uint32_t a1, uint32_t a2, uint32_t a3,
                                     uint32_t b0, uint32_t b1) {
    asm volatile("mma.sync.aligned.m16n8k8.row.col.f32.tf32.tf32.f32 "
                 "{%0,%1,%2,%3}, {%4,%5,%6,%7}, {%8,%9}, {%0,%1,%2,%3};"
                 : "+f"(c0), "+f"(c1), "+f"(c2), "+f"(c3)
                 : "r"(a0), "r"(a1), "r"(a2), "r"(a3), "r"(b0), "r"(b1));
}

// ---------------- bf16 helpers (recurrence) ----------------
__device__ __forceinline__ void mma16bf(float& c0, float& c1, float& c2, float& c3,
                                        uint32_t a0, uint32_t a1, uint32_t a2, uint32_t a3,
                                        uint32_t b0, uint32_t b1) {
    asm volatile("mma.sync.aligned.m16n8k16.row.col.f32.bf16.bf16.f32 "
                 "{%0,%1,%2,%3}, {%4,%5,%6,%7}, {%8,%9}, {%0,%1,%2,%3};"
                 : "+f"(c0), "+f"(c1), "+f"(c2), "+f"(c3)
                 : "r"(a0), "r"(a1), "r"(a2), "r"(a3), "r"(b0), "r"(b1));
}
__device__ __forceinline__ uint32_t split_pair(float a, float b, uint32_t& lo) {
    __nv_bfloat16 ah = __float2bfloat16_rn(a);
    __nv_bfloat16 bh = __float2bfloat16_rn(b);
    __nv_bfloat16 al = __float2bfloat16_rn(a - __bfloat162float(ah));
    __nv_bfloat16 bl = __float2bfloat16_rn(b - __bfloat162float(bh));
    lo = (uint32_t)__bfloat16_as_ushort(al) | ((uint32_t)__bfloat16_as_ushort(bl) << 16);
    return (uint32_t)__bfloat16_as_ushort(ah) | ((uint32_t)__bfloat16_as_ushort(bh) << 16);
}
__device__ __forceinline__ uint32_t hpk(float h) {
    __nv_bfloat16 hi = __float2bfloat16_rn(h);
    __nv_bfloat16 lo = __float2bfloat16_rn(h - __bfloat162float(hi));
    return (uint32_t)__bfloat16_as_ushort(hi) | ((uint32_t)__bfloat16_as_ushort(lo) << 16);
}

// Build 4 16B chunks {hi(tq),hi(tq+4),lo(tq),lo(tq+4)} from 16 fp32 values.
__device__ __forceinline__ void make_chunks_f32(const float* v, uint4* out) {
    uint32_t hi[8], lo[8];
#pragma unroll
    for (int p = 0; p < 8; p++) hi[p] = split_pair(v[2 * p], v[2 * p + 1], lo[p]);
#pragma unroll
    for (int tq = 0; tq < 4; tq++) {
        out[tq].x = hi[tq];
        out[tq].y = hi[tq + 4];
        out[tq].z = lo[tq];
        out[tq].w = lo[tq + 4];
    }
}
// Same from 16 hpack-packed u32 values (hi|lo<<16).
__device__ __forceinline__ void make_chunks_pk(const uint32_t* w, uint4* out) {
#pragma unroll
    for (int tq = 0; tq < 4; tq++) {
        const uint32_t a = w[2 * tq],     b = w[2 * tq + 1];
        const uint32_t c = w[2 * tq + 8], d = w[2 * tq + 9];
        out[tq].x = __byte_perm(a, b, 0x5410);
        out[tq].y = __byte_perm(c, d, 0x5410);
        out[tq].z = __byte_perm(a, b, 0x7632);
        out[tq].w = __byte_perm(c, d, 0x7632);
    }
}

// ============================================================================
// tf32 tensor-core GEMM, 2-stage SMEM double buffering (unchanged, passing).
// ============================================================================
__global__ __launch_bounds__(256) void gemm_tf32(
    const float* __restrict__ A, const float* __restrict__ W,
    const float* __restrict__ bias1, const float* __restrict__ bias2,
    float* __restrict__ C, int K, int N, int xremap)
{
    __shared__ __align__(16) float As[2][128 * GS];
    __shared__ __align__(16) float Bs[2][128 * GS];

    const int m0 = blockIdx.x * 128;
    const int n0 = blockIdx.y * 128;
    const int tid = threadIdx.x;
    const int lane = tid & 31;
    const int warp = tid >> 5;
    const int gid = lane >> 2;
    const int tig = lane & 3;
    const int wm = (warp >> 2) * 64;
    const int wn = (warp & 3) * 32;

    const int srow = tid >> 1;
    const int skoff = (tid & 1) * 8;
    int arow = m0 + srow;
    if (xremap) {
        const int b = arow & (B_DIM - 1);
        const int t = arow >> 7;
        arow = b * T_DIM + t;
    }
    const float* ag = A + (long)arow * K + skoff;
    const float* bg = W + (long)(n0 + srow) * K + skoff;
    const int soff = srow * GS + skoff;

    float acc[4][4][4];
#pragma unroll
    for (int i = 0; i < 4; i++)
#pragma unroll
        for (int j = 0; j < 4; j++)
#pragma unroll
            for (int v = 0; v < 4; v++) acc[i][j][v] = 0.f;

    {
        float4 pa0 = *(const float4*)(ag);
        float4 pa1 = *(const float4*)(ag + 4);
        float4 pb0 = *(const float4*)(bg);
        float4 pb1 = *(const float4*)(bg + 4);
        st8tf_ilv(&As[0][soff], pa0, pa1);
        st8tf_ilv(&Bs[0][soff], pb0, pb1);
    }
    __syncthreads();

    const int nch = K >> 4;
    for (int c = 0; c < nch; c++) {
        const int s = c & 1;
        const bool more = (c + 1 < nch);
        float4 na0, na1, nb0, nb1;
        if (more) {
            const int ko = (c + 1) << 4;
            na0 = *(const float4*)(ag + ko);
            na1 = *(const float4*)(ag + ko + 4);
            nb0 = *(const float4*)(bg + ko);
            nb1 = *(const float4*)(bg + ko + 4);
        }
#pragma unroll
        for (int ks = 0; ks < 16; ks += 8) {
            const int kb = ks + 2 * tig;
            float2 alo[4], ahi[4], bf[4];
#pragma unroll
            for (int i = 0; i < 4; i++) {
                const float* ap = &As[s][(wm + i * 16 + gid) * GS + kb];
                alo[i] = *(const float2*)ap;
                ahi[i] = *(const float2*)(ap + 8 * GS);
            }
#pragma unroll
            for (int j = 0; j < 4; j++)
                bf[j] = *(const float2*)&Bs[s][(wn + j * 8 + gid) * GS + kb];
#pragma unroll
            for (int i = 0; i < 4; i++)
#pragma unroll
                for (int j = 0; j < 4; j++)
                    mma8(acc[i][j][0], acc[i][j][1], acc[i][j][2], acc[i][j][3],
                         __float_as_uint(alo[i].x), __float_as_uint(ahi[i].x),
                         __float_as_uint(alo[i].y), __float_as_uint(ahi[i].y),
                         __float_as_uint(bf[j].x), __float_as_uint(bf[j].y));
        }
        if (more) {
            st8tf_ilv(&As[s ^ 1][soff], na0, na1);
            st8tf_ilv(&Bs[s ^ 1][soff], nb0, nb1);
        }
        __syncthreads();
    }

#pragma unroll
    for (int j = 0; j < 4; j++) {
        const int n = n0 + wn + j * 8 + 2 * tig;
        float bz0 = bias1[n], bz1 = bias1[n + 1];
        if (bias2) { bz0 += bias2[n]; bz1 += bias2[n + 1]; }
#pragma unroll
        for (int i = 0; i < 4; i++) {
            const int m = m0 + wm + i * 16 + gid;
            float2 o1; o1.x = acc[i][j][0] + bz0; o1.y = acc[i][j][1] + bz1;
            float2 o2; o2.x = acc[i][j][2] + bz0; o2.y = acc[i][j][3] + bz1;
            *(float2*)(C + (long)m * N + n) = o1;
            *(float2*)(C + (long)(m + 8) * N + n) = o2;
        }
    }
}

// ============================================================================
// Group barrier: 32 co-resident blocks sharing one bb (batch range).
// ============================================================================
__device__ __forceinline__ void group_barrier(int grp)
{
    __threadfence();
    __syncthreads();
    if (threadIdx.x == 0) {
        volatile unsigned int* genp = &g_bar_gen4[grp * 32];
        const unsigned g = *genp;
        const unsigned a = atomicAdd(&g_bar_cnt4[grp * 32], 1u);
        if (a == GRP_BLKS - 1) {
            g_bar_cnt4[grp * 32] = 0;
            __threadfence();
            *genp = g + 1u;
        } else {
            while (*genp == g) { }
        }
    }
    __syncthreads();
}

// ============================================================================
// Persistent LSTM layer, bf16-split tensor cores, 512 threads / 16 warps.
// Warp w: gate g = w&3, k-quarter kq = w>>2 (4 warps/SMSP -> latency hiding).
// W fragments in registers (areg[8][2], 64 regs). Per k-chunk per warp:
// 4 x (LDS.128 + 3 HMMA). Partial gates per k-quarter -> 4 gx planes,
// summed in the activation phase (1 batch per thread).
// SMEM: phase1 W staging 135 KB; phase2 hs 67 KB + gx 37 KB -> 1 block/SM.
// ============================================================================
__global__ __launch_bounds__(512, 1) void lstm_layer_kernel(
    const float* __restrict__ h0, const float* __restrict__ c0,
    const float* __restrict__ Whh, const float* __restrict__ gates,
    float* __restrict__ seq, uint32_t* __restrict__ hpack,
    float* __restrict__ hT, float* __restrict__ cT)
{
    extern __shared__ uint32_t smem[];
    uint32_t* ws = smem;                       // phase 1: [64][RSTR]
    uint32_t* hs = smem;                       // phase 2: [32][RSTR]
    float*    gx = (float*)(smem + 32 * RSTR); // phase 2: [4][64][GXS]

    const int tid = threadIdx.x;
    const int lane = tid & 31;
    const int warp = tid >> 5;                 // 0..15
    const int g = warp & 3;                    // gate
    const int kq = warp >> 2;                  // k-quarter 0..3
    const int fg = lane >> 2;                  // fragment group 0..7
    const int tq = lane & 3;

    const int mb = blockIdx.x & 31;
    const int bb = blockIdx.x >> 5;            // barrier group
    const int m0 = mb * 16;
    const int b0 = bb * 32;

    // ---- phase 1: stage W slice into SMEM chunk layout (one-time)
#pragma unroll
    for (int i = 0; i < 4; i++) {
        const int cell = tid + 512 * i;
        const int r = cell >> 5;               // local row 0..63
        const int ks = cell & 31;              // k-chunk 0..31
        const int wg = r >> 4, mli = r & 15;
        const float* wrow = Whh + (long)(wg * HID + m0 + mli) * HID + ks * 16;
        float v[16];
#pragma unroll
        for (int q = 0; q < 4; q++) *(float4*)(v + 4 * q) = *(const float4*)(wrow + 4 * q);
        uint4 ck[4];
        make_chunks_f32(v, ck);
        uint32_t* dst = ws + r * RSTR + ks * 16;
#pragma unroll
        for (int q = 0; q < 4; q++) *(uint4*)(dst + 4 * q) = ck[q];
    }
    __syncthreads();

    // ---- preload A fragments into registers (loop-invariant across t)
    const int ks0 = kq * 8;
    uint4 areg[8][2];
    {
        const uint32_t* wbase = ws + (g * 16) * RSTR;
#pragma unroll
        for (int i = 0; i < 8; i++) {
            const int off = (ks0 + i) * 16 + tq * 4;
            areg[i][0] = *(const uint4*)(wbase + fg * RSTR + off);
            areg[i][1] = *(const uint4*)(wbase + (fg + 8) * RSTR + off);
        }
    }
    __syncthreads();   // ws reads done; smem reused as hs/gx

    // activation roles: thread = (ml 0..15, bh 0..31) -> 1 batch
    const int ml = tid & 15;
    const int bh = tid >> 4;
    const int m = m0 + ml;
    const int b = b0 + bh;

    float creg = c0[(long)b * HID + m];

    for (int t = 0; t < T_DIM; t++) {
        // prefetch this step's precomputed gate contributions
        const float* pre = gates + (long)t * B_DIM * G4 + (long)b * G4 + m;
        float pg[4];
#pragma unroll
        for (int gg = 0; gg < 4; gg++)
            pg[gg] = __ldcg(pre + (gg << 9));

        // ---- stage h(t-1): 1024 cells / 512 threads
        if (t == 0) {
#pragma unroll
            for (int i = 0; i < 2; i++) {
                const int cell = tid + 512 * i;
                const int sb = cell >> 5;
                const int ks = cell & 31;
                const float* hrow = h0 + (long)(b0 + sb) * HID + ks * 16;
                float v[16];
#pragma unroll
                for (int q = 0; q < 4; q++) *(float4*)(v + 4 * q) = __ldcg((const float4*)(hrow + 4 * q));
                uint4 ck[4];
                make_chunks_f32(v, ck);
                uint32_t* dst = hs + sb * RSTR + ks * 16;
#pragma unroll
                for (int q = 0; q < 4; q++) *(uint4*)(dst + 4 * q) = ck[q];
            }
        } else {
#pragma unroll
            for (int i = 0; i < 2; i++) {
                const int cell = tid + 512 * i;
                const int sb = cell >> 5;
                const int ks = cell & 31;
                const uint32_t* hrow = hpack + (long)(b0 + sb) * HID + ks * 16;
                uint32_t u[16];
#pragma unroll
                for (int q = 0; q < 4; q++) *(uint4*)(u + 4 * q) = __ldcg((const uint4*)(hrow + 4 * q));
                uint4 ck[4];
                make_chunks_pk(u, ck);
                uint32_t* dst = hs + sb * RSTR + ks * 16;
#pragma unroll
                for (int q = 0; q < 4; q++) *(uint4*)(dst + 4 * q) = ck[q];
            }
        }
        __syncthreads();   // hs ready

        // ---- mma: warp computes gate g, k-quarter kq, all 32 batches
        float acc[4][4];
#pragma unroll
        for (int j = 0; j < 4; j++)
#pragma unroll
            for (int v = 0; v < 4; v++) acc[j][v] = 0.f;

#pragma unroll
        for (int i = 0; i < 8; i++) {
            const int off = (ks0 + i) * 16 + tq * 4;
            const uint4 A0 = areg[i][0];
            const uint4 A1 = areg[i][1];
#pragma unroll
            for (int j = 0; j < 4; j++) {
                const uint4 Bv = *(const uint4*)(hs + (8 * j + fg) * RSTR + off);
                mma16bf(acc[j][0], acc[j][1], acc[j][2], acc[j][3],
                        A0.x, A1.x, A0.y, A1.y, Bv.x, Bv.y);   // hi*hi
                mma16bf(acc[j][0], acc[j][1], acc[j][2], acc[j][3],
                        A0.x, A1.x, A0.y, A1.y, Bv.z, Bv.w);   // hi*lo
                mma16bf(acc[j][0], acc[j][1], acc[j][2], acc[j][3],
                        A0.z, A1.z, A0.w, A1.w, Bv.x, Bv.y);   // lo*hi
            }
        }

        // ---- write partial gates to this k-quarter's exchange plane
        float* gxp = gx + kq * (64 * GXS);
#pragma unroll
        for (int j = 0; j < 4; j++) {
            float2 lo2; lo2.x = acc[j][0]; lo2.y = acc[j][1];
            float2 hi2; hi2.x = acc[j][2]; hi2.y = acc[j][3];
            *(float2*)&gxp[(g * 16 + fg) * GXS + 8 * j + 2 * tq] = lo2;
            *(float2*)&gxp[(g * 16 + fg + 8) * GXS + 8 * j + 2 * tq] = hi2;
        }
        __syncthreads();

        // ---- activations: sum 4 k-quarter partials, update state, write h
        float gate[4];
#pragma unroll
        for (int gg = 0; gg < 4; gg++) {
            const int row = (gg * 16 + ml) * GXS + bh;
            gate[gg] = (gx[row] + gx[64 * GXS + row])
                     + (gx[2 * 64 * GXS + row] + gx[3 * 64 * GXS + row]);
        }

        const float gi = gate[0] + pg[0];
        const float gf = gate[1] + pg[1];
        const float gg = gate[2] + pg[2];
        const float go = gate[3] + pg[3];
        const float i_ = __fdividef(1.f, 1.f + __expf(-gi));
        const float f_ = __fdividef(1.f, 1.f + __expf(-gf));
        const float g_ = tanhf(gg);
        const float o_ = __fdividef(1.f, 1.f + __expf(-go));
        const float c = f_ * creg + i_ * g_;
        creg = c;
        const float h = o_ * tanhf(c);
        hpack[(long)b * HID + m] = hpk(h);
        seq[(long)t * STATE + (long)b * HID + m] = h;
        if (t == T_DIM - 1) {
            hT[(long)b * HID + m] = h;
            cT[(long)b * HID + m] = c;
        }

        group_barrier(bb);   // only the 32 blocks sharing this batch range
    }
}

// ============================================================================
// LayerNorm + (t,b)->(b,t) transpose (unchanged).
// ============================================================================
__global__ __launch_bounds__(256) void ln_out_kernel(
    const float* __restrict__ X, const float* __restrict__ gamma,
    const float* __restrict__ beta, float* __restrict__ out)
{
    const int row = blockIdx.x;
    const float* x = X + (long)row * OUT_DIM;
    const int tid = threadIdx.x;

    const float v0 = x[tid];
    const float v1 = x[tid + 256];
    const float v2 = x[tid + 512];

    __shared__ float red[8];
    __shared__ float s_mu, s_rs;

    float s = v0 + v1 + v2;
#pragma unroll
    for (int o = 16; o > 0; o >>= 1) s += __shfl_down_sync(0xffffffffu, s, o);
    if ((tid & 31) == 0) red[tid >> 5] = s;
    __syncthreads();
    if (tid == 0) {
        float tot = 0.f;
#pragma unroll
        for (int i = 0; i < 8; i++) tot += red[i];
        s_mu = tot * (1.f / OUT_DIM);
    }
    __syncthreads();
    const float mu = s_mu;
    const float d0 = v0 - mu, d1 = v1 - mu, d2 = v2 - mu;

    float q = d0 * d0 + d1 * d1 + d2 * d2;
#pragma unroll
    for (int o = 16; o > 0; o >>= 1) q += __shfl_down_sync(0xffffffffu, q, o);
    if ((tid & 31) == 0) red[tid >> 5] = q;
    __syncthreads();
    if (tid == 0) {
        float tot = 0.f;
#pragma unroll
        for (int i = 0; i < 8; i++) tot += red[i];
        s_rs = rsqrtf(tot * (1.f / OUT_DIM) + 1e-5f);
    }
    __syncthreads();
    const float rs = s_rs;

    const int b = row & (B_DIM - 1);
    const int t = row >> 7;
    float* o = out + (long)(b * T_DIM + t) * OUT_DIM;
    o[tid]       = d0 * rs * gamma[tid]       + beta[tid];
    o[tid + 256] = d1 * rs * gamma[tid + 256] + beta[tid + 256];
    o[tid + 512] = d2 * rs * gamma[tid + 512] + beta[tid + 512];
}

// ============================================================================
extern "C" void kernel_launch(void* const* d_in, const int* in_sizes, int n_in,
                              void* d_out, int out_size)
{
    const float* x     = (const float*)d_in[0];
    const float* h0    = (const float*)d_in[1];
    const float* c0    = (const float*)d_in[2];
    const float* W_in  = (const float*)d_in[3];
    const float* b_in  = (const float*)d_in[4];
    const float* W_ih  = (const float*)d_in[5];
    const float* W_hh  = (const float*)d_in[6];
    const float* b_ih  = (const float*)d_in[7];
    const float* b_hh  = (const float*)d_in[8];
    const float* W_out = (const float*)d_in[9];
    const float* b_out = (const float*)d_in[10];
    const float* ln_g  = (const float*)d_in[11];
    const float* ln_b  = (const float*)d_in[12];
    float* out = (float*)d_out;

    float *seqA, *seqB, *gates, *outp;
    uint32_t* hpack;
    cudaGetSymbolAddress((void**)&seqA, g_seqA);
    cudaGetSymbolAddress((void**)&seqB, g_seqB);
    cudaGetSymbolAddress((void**)&gates, g_gates);
    cudaGetSymbolAddress((void**)&outp, g_outp);
    cudaGetSymbolAddress((void**)&hpack, g_hpack);

    const int ws_bytes = 64 * RSTR * 4;                           // 135168
    const int ph2_bytes = 32 * RSTR * 4 + 4 * 64 * GXS * 4;       // 104448
    const int lstm_smem = ws_bytes > ph2_bytes ? ws_bytes : ph2_bytes;
    cudaFuncSetAttribute(lstm_layer_kernel,
                         cudaFuncAttributeMaxDynamicSharedMemorySize, lstm_smem);

    const long OUT_ELEMS = (long)B_DIM * T_DIM * OUT_DIM;

    // 1) input projection with (b,t)->(t,b) transpose (tf32 TC)
    gemm_tf32<<<dim3(ROWS / 128, HID / 128), 256>>>(x, W_in, b_in, nullptr, seqA,
                                                    INP_DIM, HID, 1);

    for (int l = 0; l < NL; l++) {
        const float* in = (l & 1) ? seqB : seqA;
        float* outSeq   = (l & 1) ? seqA : seqB;

        // 2a) parallel: gates = in @ W_ih[l]^T + b_ih[l] + b_hh[l] (tf32 TC)
        gemm_tf32<<<dim3(ROWS / 128, G4 / 128), 256>>>(
            in, W_ih + (long)l * G4 * HID, b_ih + l * G4, b_hh + l * G4,
            gates, HID, G4, 0);

        // 2b) serial recurrence: persistent, bf16-split TC, 16 warps
        lstm_layer_kernel<<<NBLK, 512, lstm_smem>>>(
            h0 + (long)l * STATE, c0 + (long)l * STATE,
            W_hh + (long)l * G4 * HID, gates, outSeq, hpack,
            out + OUT_ELEMS + (long)l * STATE,
            out + OUT_ELEMS + (long)NL * STATE + (long)l * STATE);
    }

    // 3) output projection (tf32 TC)
    gemm_tf32<<<dim3(ROWS / 128, OUT_DIM / 128), 256>>>(seqA, W_out, b_out, nullptr,
                                                        outp, HID, OUT_DIM, 0);

    // 4) layernorm + transpose into d_out
    ln_out_kernel<<<ROWS, 256>>>(outp, ln_g, ln_b, out);
}